// round 1
// baseline (speedup 1.0000x reference)
#include <cuda_runtime.h>
#include <math.h>

namespace nys {

constexpr int B = 16, L = 1000, D = 512, H = 8, DH = 64;
constexpr int N = 1024, M = 256, PADN = 24, DEPTH = 6, FF = 2048, KC = 33;
constexpr int BH = B * H;
constexpr float SCALE = 0.125f;   // DH^-0.5

// ------------------------- scratch (static device memory) -------------------
__device__ float g_h   [B * L * D];
__device__ float g_xp  [B * N * D];
__device__ float g_x2  [B * L * D];
__device__ float g_qkv [B * N * 3 * D];
__device__ float g_ql  [BH * M * DH];
__device__ float g_kl  [BH * M * DH];
__device__ float g_attn1[BH * N * M];
__device__ float g_attn3[BH * M * N];
__device__ float g_attn2[BH * M * M];
__device__ float g_z   [BH * M * M];
__device__ float g_z2  [BH * M * M];
__device__ float g_xz  [BH * M * M];
__device__ float g_u1  [BH * M * M];
__device__ float g_u3  [BH * M * M];
__device__ float g_av  [BH * M * DH];
__device__ float g_t   [BH * N * M];
__device__ float g_ctx [B * N * D];
__device__ float g_ff  [B * L * FF];
__device__ float g_scal[2];
__device__ float g_part[B * 64];

// ------------------------- block reduction helpers --------------------------
__device__ __forceinline__ float blkSum(float v, float* sh) {
    int lane = threadIdx.x & 31, w = threadIdx.x >> 5;
#pragma unroll
    for (int o = 16; o; o >>= 1) v += __shfl_xor_sync(0xffffffffu, v, o);
    if (lane == 0) sh[w] = v;
    __syncthreads();
    if (w == 0) {
        float t = (lane < (int)(blockDim.x >> 5)) ? sh[lane] : 0.f;
#pragma unroll
        for (int o = 16; o; o >>= 1) t += __shfl_xor_sync(0xffffffffu, t, o);
        if (lane == 0) sh[32] = t;
    }
    __syncthreads();
    float r = sh[32];
    __syncthreads();
    return r;
}

__device__ __forceinline__ float blkMax(float v, float* sh) {
    int lane = threadIdx.x & 31, w = threadIdx.x >> 5;
#pragma unroll
    for (int o = 16; o; o >>= 1) v = fmaxf(v, __shfl_xor_sync(0xffffffffu, v, o));
    if (lane == 0) sh[w] = v;
    __syncthreads();
    if (w == 0) {
        float t = (lane < (int)(blockDim.x >> 5)) ? sh[lane] : -3.4e38f;
#pragma unroll
        for (int o = 16; o; o >>= 1) t = fmaxf(t, __shfl_xor_sync(0xffffffffu, t, o));
        if (lane == 0) sh[32] = t;
    }
    __syncthreads();
    float r = sh[32];
    __syncthreads();
    return r;
}

// ------------------------- generic batched SGEMM -----------------------------
// C = alpha * A(@/@T)B  [+ escale*E] [+ bias] [gelu] [accumulate / row-remap]
// batch z decomposed as (bb = z/Hd, hh = z%Hd) with per-operand strides.
// All dims must be multiples of tile sizes (they are, by construction).
template <int BM, int BN, int TM, int TN>
__global__ void __launch_bounds__(256) sgemm(
    int Kdim,
    const float* __restrict__ A, int lda, long sA1, long sA2,
    const float* __restrict__ Bm, int ldb, long sB1, long sB2, int transB,
    float* __restrict__ C, int ldc, long sC1, long sC2,
    int Hd, float alpha,
    const float* __restrict__ bias, int gelu,
    const float* __restrict__ E, float escale,
    int accumulate, int remap)
{
    constexpr int BK = 16;
    __shared__ float As[BK][BM];
    __shared__ float Bs[BK][BN];
    int tid = threadIdx.x;
    int m0 = blockIdx.y * BM, n0 = blockIdx.x * BN;
    int z = blockIdx.z;
    int bb = z / Hd, hh = z - bb * Hd;
    const float* Ap = A + (long)bb * sA1 + (long)hh * sA2;
    const float* Bp = Bm + (long)bb * sB1 + (long)hh * sB2;
    long coff = (long)bb * sC1 + (long)hh * sC2;

    float acc[TM][TN];
#pragma unroll
    for (int i = 0; i < TM; i++)
#pragma unroll
        for (int j = 0; j < TN; j++) acc[i][j] = 0.f;

    int tx = tid % (BN / TN);
    int ty = tid / (BN / TN);

    for (int k0 = 0; k0 < Kdim; k0 += BK) {
#pragma unroll
        for (int i = 0; i < (BM * BK) / 256; i++) {
            int lin = i * 256 + tid;
            int m = lin >> 4, k = lin & 15;
            As[k][m] = Ap[(long)(m0 + m) * lda + k0 + k];
        }
        if (transB) {
#pragma unroll
            for (int i = 0; i < (BN * BK) / 256; i++) {
                int lin = i * 256 + tid;
                int n = lin >> 4, k = lin & 15;
                Bs[k][n] = Bp[(long)(n0 + n) * ldb + k0 + k];
            }
        } else {
#pragma unroll
            for (int i = 0; i < (BN * BK) / 256; i++) {
                int lin = i * 256 + tid;
                int k = lin / BN, n = lin % BN;
                Bs[k][n] = Bp[(long)(k0 + k) * ldb + n0 + n];
            }
        }
        __syncthreads();
#pragma unroll
        for (int kk = 0; kk < BK; kk++) {
            float a[TM], b[TN];
#pragma unroll
            for (int i = 0; i < TM; i++) a[i] = As[kk][ty * TM + i];
#pragma unroll
            for (int j = 0; j < TN; j++) b[j] = Bs[kk][tx * TN + j];
#pragma unroll
            for (int i = 0; i < TM; i++)
#pragma unroll
                for (int j = 0; j < TN; j++) acc[i][j] = fmaf(a[i], b[j], acc[i][j]);
        }
        __syncthreads();
    }

#pragma unroll
    for (int i = 0; i < TM; i++) {
        int m = m0 + ty * TM + i;
#pragma unroll
        for (int j = 0; j < TN; j++) {
            int n = n0 + tx * TN + j;
            float v = alpha * acc[i][j];
            if (E) v += escale * E[coff + (long)m * ldc + n];
            if (bias) v += bias[n];
            if (gelu) v = 0.5f * v * (1.0f + erff(v * 0.70710678118654752f));
            if (remap) {
                // rows are b*N + n_seq; drop left pad, residual-add into g_h
                int bI = m >> 10;           // N = 1024
                int nn = m & 1023;
                if (nn >= PADN)
                    C[((long)bI * L + (nn - PADN)) * ldc + n] += v;
            } else {
                long idx = coff + (long)m * ldc + n;
                if (accumulate) C[idx] += v; else C[idx] = v;
            }
        }
    }
}

// ------------------------- elementwise / reduction kernels -------------------
__global__ void embed_kernel(const int* __restrict__ x, const float* __restrict__ enc,
                             const float* __restrict__ pos, float* __restrict__ h) {
    long idx = (long)blockIdx.x * 256 + threadIdx.x;   // B*L*D total
    int d = (int)(idx % D);
    long bl = idx / D;
    int l = (int)(bl % L);
    h[idx] = enc[(long)x[bl] * D + d] + pos[(long)l * D + d];
}

__global__ void ln_pad_kernel(const float* __restrict__ src, float* __restrict__ dst,
                              const float* __restrict__ s, const float* __restrict__ bia) {
    int row = blockIdx.x;                 // B*N rows
    int b = row >> 10, n = row & 1023;
    int tid = threadIdx.x;                // 256 threads, 2 elems each
    float* out = dst + (long)row * D;
    if (n < PADN) { out[tid] = 0.f; out[tid + 256] = 0.f; return; }
    const float* in = src + ((long)b * L + (n - PADN)) * D;
    __shared__ float sh[33];
    float v0 = in[tid], v1 = in[tid + 256];
    float mu = blkSum(v0 + v1, sh) * (1.0f / D);
    float d0 = v0 - mu, d1 = v1 - mu;
    float var = blkSum(d0 * d0 + d1 * d1, sh) * (1.0f / D);
    float r = rsqrtf(var + 1e-5f);
    out[tid]       = d0 * r * s[tid]       + bia[tid];
    out[tid + 256] = d1 * r * s[tid + 256] + bia[tid + 256];
}

__global__ void ln_kernel(const float* __restrict__ src, float* __restrict__ dst,
                          const float* __restrict__ s, const float* __restrict__ bia) {
    long row = blockIdx.x;                // B*L rows
    int tid = threadIdx.x;
    const float* in = src + row * D;
    float* out = dst + row * D;
    __shared__ float sh[33];
    float v0 = in[tid], v1 = in[tid + 256];
    float mu = blkSum(v0 + v1, sh) * (1.0f / D);
    float d0 = v0 - mu, d1 = v1 - mu;
    float var = blkSum(d0 * d0 + d1 * d1, sh) * (1.0f / D);
    float r = rsqrtf(var + 1e-5f);
    out[tid]       = d0 * r * s[tid]       + bia[tid];
    out[tid + 256] = d1 * r * s[tid + 256] + bia[tid + 256];
}

__global__ void landmark_kernel(const float* __restrict__ qkv,
                                float* __restrict__ ql, float* __restrict__ kl) {
    int idx = blockIdx.x * 256 + threadIdx.x;    // BH*M*DH total
    int d = idx & 63;
    int m = (idx >> 6) & (M - 1);
    int bh = idx >> 14;
    int b = bh >> 3, h = bh & 7;
    const float* base = qkv + ((long)(b * N + m * 4)) * 1536 + h * 64 + d;
    float sq = 0.f, sk = 0.f;
#pragma unroll
    for (int j = 0; j < 4; j++) { sq += base[j * 1536]; sk += base[j * 1536 + 512]; }
    ql[idx] = sq * 0.25f;
    kl[idx] = sk * 0.25f;
}

template <int W>
__global__ void softmax_kernel(float* __restrict__ x) {
    constexpr int PT = W / 256;
    long base = (long)blockIdx.x * W;
    int tid = threadIdx.x;
    __shared__ float sh[33];
    float v[PT];
    float mx = -3.4e38f;
#pragma unroll
    for (int p = 0; p < PT; p++) { v[p] = x[base + tid + p * 256]; mx = fmaxf(mx, v[p]); }
    mx = blkMax(mx, sh);
    float s = 0.f;
#pragma unroll
    for (int p = 0; p < PT; p++) { v[p] = expf(v[p] - mx); s += v[p]; }
    s = blkSum(s, sh);
    float inv = 1.0f / s;
#pragma unroll
    for (int p = 0; p < PT; p++) x[base + tid + p * 256] = v[p] * inv;
}

__global__ void scal_init_kernel(float* scal) {
    if (threadIdx.x < 2) scal[threadIdx.x] = 0.f;
}

__global__ void absrowmax_kernel(const float* __restrict__ x, float* scal) {
    long base = (long)blockIdx.x * M;     // BH*M rows
    __shared__ float sh[33];
    float v = fabsf(x[base + threadIdx.x]);
    float s = blkSum(v, sh);
    if (threadIdx.x == 0)
        atomicMax((unsigned int*)&scal[0], __float_as_uint(s));
}

__global__ void abscolmax_kernel(const float* __restrict__ x, float* scal) {
    const float* p = x + (long)blockIdx.x * M * M;   // BH batches
    int j = threadIdx.x;
    float s = 0.f;
    for (int i = 0; i < M; i++) s += fabsf(p[i * M + j]);
    __shared__ float sh[33];
    float m = blkMax(s, sh);
    if (threadIdx.x == 0)
        atomicMax((unsigned int*)&scal[1], __float_as_uint(m));
}

__global__ void zinit_kernel(const float* __restrict__ x, const float* __restrict__ scal,
                             float* __restrict__ z) {
    long idx = (long)blockIdx.x * 256 + threadIdx.x;  // BH*M*M
    float inv = 1.0f / (scal[0] * scal[1]);
    int j = (int)(idx & 255);
    int i = (int)((idx >> 8) & 255);
    long bh = idx >> 16;
    z[idx] = x[(bh << 16) + (long)j * M + i] * inv;
}

__global__ void conv_kernel(const float* __restrict__ qkv, const float* __restrict__ ck,
                            float* __restrict__ ctx) {
    __shared__ float sv[160 * 64];
    __shared__ float sck[KC];
    int bh = blockIdx.y;
    int b = bh >> 3, h = bh & 7;
    int n0 = blockIdx.x * 128;
    int tid = threadIdx.x;
    if (tid < KC) sck[tid] = ck[h * KC + tid];
    for (int i = tid; i < 160 * 64; i += 256) {
        int r = i >> 6, d = i & 63;
        int n = n0 - 16 + r;
        float v = 0.f;
        if (n >= 0 && n < N) v = qkv[((long)(b * N + n)) * 1536 + 1024 + h * 64 + d];
        sv[i] = v;
    }
    __syncthreads();
    for (int o = tid; o < 128 * 64; o += 256) {
        int nl = o >> 6, d = o & 63;
        float s = 0.f;
#pragma unroll
        for (int t = 0; t < KC; t++) s += sck[t] * sv[(nl + t) * 64 + d];
        ctx[((long)(b * N + n0 + nl)) * D + h * 64 + d] = s;
    }
}

__global__ void final_partial_kernel(const float* __restrict__ h, const float* __restrict__ fw,
                                     float* __restrict__ part) {
    int b = blockIdx.y, c = blockIdx.x;   // 64 chunks per batch
    const int CHK = (L * D) / 64;         // 8000
    long base = (long)b * L * D;
    float s = 0.f;
    for (int i = c * CHK + threadIdx.x; i < (c + 1) * CHK; i += 256)
        s += h[base + i] * fw[i];
    __shared__ float sh[33];
    s = blkSum(s, sh);
    if (threadIdx.x == 0) part[b * 64 + c] = s;
}

__global__ void final_reduce_kernel(const float* __restrict__ part, const float* __restrict__ fb,
                                    float* __restrict__ out) {
    int b = blockIdx.x;
    int t = threadIdx.x;  // 32
    float v = part[b * 64 + t] + part[b * 64 + t + 32];
#pragma unroll
    for (int o = 16; o; o >>= 1) v += __shfl_xor_sync(0xffffffffu, v, o);
    if (t == 0) out[b] = v + fb[0];
}

} // namespace nys

// ------------------------- host orchestration --------------------------------
static float* nys_sym(const void* s) {
    void* p = nullptr;
    cudaGetSymbolAddress(&p, s);
    return (float*)p;
}

static void gemm(int cfg128, int Mdim, int Ndim, int K,
                 const float* A, int lda, long sA1, long sA2,
                 const float* Bm, int ldb, long sB1, long sB2, int tB,
                 float* C, int ldc, long sC1, long sC2,
                 int batch, int Hd, float alpha,
                 const float* bias, int gelu, const float* E, float es,
                 int acc, int remap) {
    if (cfg128) {
        dim3 g(Ndim / 128, Mdim / 128, batch);
        nys::sgemm<128, 128, 8, 8><<<g, 256>>>(K, A, lda, sA1, sA2, Bm, ldb, sB1, sB2, tB,
                                               C, ldc, sC1, sC2, Hd, alpha, bias, gelu, E, es, acc, remap);
    } else {
        dim3 g(Ndim / 64, Mdim / 64, batch);
        nys::sgemm<64, 64, 4, 4><<<g, 256>>>(K, A, lda, sA1, sA2, Bm, ldb, sB1, sB2, tB,
                                             C, ldc, sC1, sC2, Hd, alpha, bias, gelu, E, es, acc, remap);
    }
}

extern "C" void kernel_launch(void* const* d_in, const int* in_sizes, int n_in,
                              void* d_out, int out_size) {
    using namespace nys;
    (void)in_sizes; (void)n_in; (void)out_size;

    const int*   xin    = (const int*)  d_in[0];
    const float* enc    = (const float*)d_in[1];
    const float* pos    = (const float*)d_in[2];
    const float* ln1_s  = (const float*)d_in[3];
    const float* ln1_b  = (const float*)d_in[4];
    const float* qkv_w  = (const float*)d_in[5];
    const float* out_w  = (const float*)d_in[6];
    const float* out_b  = (const float*)d_in[7];
    const float* conv_k = (const float*)d_in[8];
    const float* ln2_s  = (const float*)d_in[9];
    const float* ln2_b  = (const float*)d_in[10];
    const float* ff_w1  = (const float*)d_in[11];
    const float* ff_b1  = (const float*)d_in[12];
    const float* ff_w2  = (const float*)d_in[13];
    const float* ff_b2  = (const float*)d_in[14];
    const float* fin_w  = (const float*)d_in[15];
    const float* fin_b  = (const float*)d_in[16];
    float* out = (float*)d_out;

    float* h     = nys_sym(g_h);
    float* xp    = nys_sym(g_xp);
    float* x2    = nys_sym(g_x2);
    float* qkv   = nys_sym(g_qkv);
    float* ql    = nys_sym(g_ql);
    float* kl    = nys_sym(g_kl);
    float* attn1 = nys_sym(g_attn1);
    float* attn3 = nys_sym(g_attn3);
    float* attn2 = nys_sym(g_attn2);
    float* zb    = nys_sym(g_z);
    float* zb2   = nys_sym(g_z2);
    float* xz    = nys_sym(g_xz);
    float* u1    = nys_sym(g_u1);
    float* u3    = nys_sym(g_u3);
    float* av    = nys_sym(g_av);
    float* tt    = nys_sym(g_t);
    float* ctx   = nys_sym(g_ctx);
    float* ff    = nys_sym(g_ff);
    float* scal  = nys_sym(g_scal);
    float* part  = nys_sym(g_part);

    const long MM2 = (long)M * M;

    embed_kernel<<<(B * L * D) / 256, 256>>>(xin, enc, pos, h);

    for (int i = 0; i < DEPTH; i++) {
        const float* qw  = qkv_w  + (long)i * D * 3 * D;
        const float* ow  = out_w  + (long)i * D * D;
        const float* ob  = out_b  + (long)i * D;
        const float* ckp = conv_k + (long)i * H * KC;
        const float* w1  = ff_w1  + (long)i * D * FF;
        const float* b1  = ff_b1  + (long)i * FF;
        const float* w2  = ff_w2  + (long)i * FF * D;
        const float* b2  = ff_b2  + (long)i * D;

        // LN1 + left-pad into xp (B*N rows)
        ln_pad_kernel<<<B * N, 256>>>(h, xp, ln1_s + (long)i * D, ln1_b + (long)i * D);

        // qkv = xp @ qkv_w   (16384 x 1536 x 512)
        gemm(1, B * N, 3 * D, D, xp, D, 0, 0, qw, 3 * D, 0, 0, 0,
             qkv, 3 * D, 0, 0, 1, 1, 1.f, nullptr, 0, nullptr, 0.f, 0, 0);

        // landmark means (q_l unscaled; SCALE folded into logit alphas)
        landmark_kernel<<<(BH * M * DH) / 256, 256>>>(qkv, ql, kl);

        // attn1 = softmax(SCALE * q @ k_l^T)   (1024 x 256 x 64, batched bh)
        gemm(1, N, M, DH,
             qkv, 3 * D, (long)N * 3 * D, 64,
             kl, DH, (long)H * M * DH, (long)M * DH, 1,
             attn1, M, (long)H * N * M, (long)N * M,
             BH, H, SCALE, nullptr, 0, nullptr, 0.f, 0, 0);
        softmax_kernel<256><<<BH * N, 256>>>(attn1);

        // attn2 = softmax(SCALE * q_l @ k_l^T) (256 x 256 x 64)
        gemm(1, M, M, DH,
             ql, DH, (long)H * M * DH, (long)M * DH,
             kl, DH, (long)H * M * DH, (long)M * DH, 1,
             attn2, M, (long)H * M * M, MM2,
             BH, H, SCALE, nullptr, 0, nullptr, 0.f, 0, 0);
        softmax_kernel<256><<<BH * M, 256>>>(attn2);

        // attn3 = softmax(SCALE * q_l @ k^T)   (256 x 1024 x 64)
        gemm(1, M, N, DH,
             ql, DH, (long)H * M * DH, (long)M * DH,
             qkv + D, 3 * D, (long)N * 3 * D, 64, 1,
             attn3, N, (long)H * M * N, (long)M * N,
             BH, H, SCALE, nullptr, 0, nullptr, 0.f, 0, 0);
        softmax_kernel<1024><<<BH * M, 256>>>(attn3);

        // Moore-Penrose pinv of attn2 (6 iterations)
        scal_init_kernel<<<1, 32>>>(scal);
        absrowmax_kernel<<<BH * M, 256>>>(attn2, scal);
        abscolmax_kernel<<<BH, 256>>>(attn2, scal);
        zinit_kernel<<<(BH * M * M) / 256, 256>>>(attn2, scal, zb);

        float* zc = zb;
        float* zn = zb2;
        for (int it = 0; it < 6; it++) {
            // xz = x @ z
            gemm(1, M, M, M, attn2, M, MM2, 0, zc, M, MM2, 0, 0,
                 xz, M, MM2, 0, BH, 1, 1.f, nullptr, 0, nullptr, 0.f, 0, 0);
            // u1 = 7*xz - xz@xz
            gemm(1, M, M, M, xz, M, MM2, 0, xz, M, MM2, 0, 0,
                 u1, M, MM2, 0, BH, 1, -1.f, nullptr, 0, xz, 7.f, 0, 0);
            // u3 = 15*xz - xz@u1
            gemm(1, M, M, M, xz, M, MM2, 0, u1, M, MM2, 0, 0,
                 u3, M, MM2, 0, BH, 1, -1.f, nullptr, 0, xz, 15.f, 0, 0);
            // z' = 3.25*z - 0.25*z@u3
            gemm(1, M, M, M, zc, M, MM2, 0, u3, M, MM2, 0, 0,
                 zn, M, MM2, 0, BH, 1, -0.25f, nullptr, 0, zc, 3.25f, 0, 0);
            float* tmp = zc; zc = zn; zn = tmp;
        }
        // zc holds pinv(attn2) after 6 iterations (even # of swaps -> g_z)

        // av = attn3 @ v    (256 x 64 x 1024)
        gemm(0, M, DH, N,
             attn3, N, (long)H * M * N, (long)M * N,
             qkv + 2 * D, 3 * D, (long)N * 3 * D, 64, 0,
             av, DH, (long)H * M * DH, (long)M * DH,
             BH, H, 1.f, nullptr, 0, nullptr, 0.f, 0, 0);

        // conv residual into ctx (B,N,D layout)
        conv_kernel<<<dim3(N / 128, BH), 256>>>(qkv, ckp, ctx);

        // t = attn1 @ pinv  (1024 x 256 x 256)
        gemm(1, N, M, M,
             attn1, M, (long)N * M, 0,
             zc, M, MM2, 0, 0,
             tt, M, (long)N * M, 0,
             BH, 1, 1.f, nullptr, 0, nullptr, 0.f, 0, 0);

        // ctx += t @ av     (1024 x 64 x 256), strided write into (B,N,D)
        gemm(0, N, DH, M,
             tt, M, (long)H * N * M, (long)N * M,
             av, DH, (long)H * M * DH, (long)M * DH, 0,
             ctx, D, (long)N * D, 64,
             BH, H, 1.f, nullptr, 0, nullptr, 0.f, 1, 0);

        // h += (ctx @ out_w + out_b)[:, -L:]   (remap epilogue)
        gemm(1, B * N, D, D, ctx, D, 0, 0, ow, D, 0, 0, 0,
             h, D, 0, 0, 1, 1, 1.f, ob, 0, nullptr, 0.f, 0, 1);

        // FFN
        ln_kernel<<<B * L, 256>>>(h, x2, ln2_s + (long)i * D, ln2_b + (long)i * D);
        gemm(1, B * L, FF, D, x2, D, 0, 0, w1, FF, 0, 0, 0,
             ff, FF, 0, 0, 1, 1, 1.f, b1, 1, nullptr, 0.f, 0, 0);
        gemm(1, B * L, D, FF, ff, FF, 0, 0, w2, D, 0, 0, 0,
             h, D, 0, 0, 1, 1, 1.f, b2, 0, nullptr, 0.f, 1, 0);
    }

    final_partial_kernel<<<dim3(64, B), 256>>>(h, fin_w, part);
    final_reduce_kernel<<<B, 32>>>(part, fin_b, out);
}

// round 2
// speedup vs baseline: 1.3011x; 1.3011x over previous
#include <cuda_runtime.h>
#include <math.h>
#include <mma.h>

using namespace nvcuda;

namespace nys {

constexpr int B = 16, L = 1000, D = 512, H = 8, DH = 64;
constexpr int N = 1024, M = 256, PADN = 24, DEPTH = 6, FF = 2048, KC = 33;
constexpr int BH = B * H;
constexpr float SCALE = 0.125f;   // DH^-0.5

// ------------------------- scratch (static device memory) -------------------
__device__ float g_h   [B * L * D];
__device__ float g_xp  [B * N * D];
__device__ float g_x2  [B * L * D];
__device__ float g_qkv [B * N * 3 * D];
__device__ float g_ql  [BH * M * DH];
__device__ float g_kl  [BH * M * DH];
__device__ float g_attn1[BH * N * M];
__device__ float g_attn3[BH * M * N];
__device__ float g_attn2[BH * M * M];
__device__ float g_z   [BH * M * M];
__device__ float g_z2  [BH * M * M];
__device__ float g_xz  [BH * M * M];
__device__ float g_u1  [BH * M * M];
__device__ float g_u3  [BH * M * M];
__device__ float g_av  [BH * M * DH];
__device__ float g_t   [BH * N * M];
__device__ float g_ctx [B * N * D];
__device__ float g_ff  [B * L * FF];
__device__ float g_scal[2];
__device__ float g_part[B * 64];

// ------------------------- block reduction helpers --------------------------
__device__ __forceinline__ float blkSum(float v, float* sh) {
    int lane = threadIdx.x & 31, w = threadIdx.x >> 5;
#pragma unroll
    for (int o = 16; o; o >>= 1) v += __shfl_xor_sync(0xffffffffu, v, o);
    if (lane == 0) sh[w] = v;
    __syncthreads();
    if (w == 0) {
        float t = (lane < (int)(blockDim.x >> 5)) ? sh[lane] : 0.f;
#pragma unroll
        for (int o = 16; o; o >>= 1) t += __shfl_xor_sync(0xffffffffu, t, o);
        if (lane == 0) sh[32] = t;
    }
    __syncthreads();
    float r = sh[32];
    __syncthreads();
    return r;
}

__device__ __forceinline__ float blkMax(float v, float* sh) {
    int lane = threadIdx.x & 31, w = threadIdx.x >> 5;
#pragma unroll
    for (int o = 16; o; o >>= 1) v = fmaxf(v, __shfl_xor_sync(0xffffffffu, v, o));
    if (lane == 0) sh[w] = v;
    __syncthreads();
    if (w == 0) {
        float t = (lane < (int)(blockDim.x >> 5)) ? sh[lane] : -3.4e38f;
#pragma unroll
        for (int o = 16; o; o >>= 1) t = fmaxf(t, __shfl_xor_sync(0xffffffffu, t, o));
        if (lane == 0) sh[32] = t;
    }
    __syncthreads();
    float r = sh[32];
    __syncthreads();
    return r;
}

// ------------------------- tf32 tensor-core batched GEMM ---------------------
// C = alpha * A(@/@T)B  [+ escale*E] [+ bias] [gelu] [accumulate / row-remap]
// A fp32 row-major [m,k]; B fp32 row-major [k,n] (transB=0) or [n,k] (transB=1).
// fp32 -> tf32 rounding happens when staging smem tiles; fp32 accumulate.
template <int BM, int BN, int WM, int WN>
__global__ void __launch_bounds__(256) tgemm(
    int Kdim,
    const float* __restrict__ A, int lda, long sA1, long sA2,
    const float* __restrict__ Bm, int ldb, long sB1, long sB2, int transB,
    float* __restrict__ C, int ldc, long sC1, long sC2,
    int Hd, float alpha,
    const float* __restrict__ bias, int gelu,
    const float* __restrict__ E, float escale,
    int accumulate, int remap)
{
    constexpr int BK   = 32;
    constexpr int LDA  = BK + 4;      // 36 (mult of 4 for wmma)
    constexpr int LDB  = BN + 4;
    constexpr int MI   = WM / 16;
    constexpr int NI   = WN / 16;
    constexpr int WCOL = BN / WN;     // warps along n
    constexpr int NWARP = (BM / WM) * (BN / WN);
    static_assert(NWARP == 8, "8 warps");

    __shared__ float sA[BM * LDA];
    __shared__ float sB[BK * LDB];
    __shared__ float cpad[NWARP][16 * 20];   // per-warp epilogue staging

    int tid = threadIdx.x;
    int wid = tid >> 5, lane = tid & 31;
    int m0 = blockIdx.y * BM, n0 = blockIdx.x * BN;
    int z = blockIdx.z;
    int bb = z / Hd, hh = z - bb * Hd;
    const float* Ap = A + (long)bb * sA1 + (long)hh * sA2;
    const float* Bp = Bm + (long)bb * sB1 + (long)hh * sB2;
    long coff = (long)bb * sC1 + (long)hh * sC2;

    int wm0 = (wid / WCOL) * WM;
    int wn0 = (wid % WCOL) * WN;

    wmma::fragment<wmma::accumulator, 16, 16, 8, float> acc[MI][NI];
#pragma unroll
    for (int mi = 0; mi < MI; mi++)
#pragma unroll
        for (int ni = 0; ni < NI; ni++) wmma::fill_fragment(acc[mi][ni], 0.f);

    for (int k0 = 0; k0 < Kdim; k0 += BK) {
        // stage A (always [m,k] row-major), vectorized + tf32 round
#pragma unroll
        for (int i = tid; i < (BM * BK) / 4; i += 256) {
            int row = i / (BK / 4), kq = i % (BK / 4);
            float4 v = *(const float4*)(Ap + (long)(m0 + row) * lda + k0 + kq * 4);
            float* dst = &sA[row * LDA + kq * 4];
            dst[0] = wmma::__float_to_tf32(v.x);
            dst[1] = wmma::__float_to_tf32(v.y);
            dst[2] = wmma::__float_to_tf32(v.z);
            dst[3] = wmma::__float_to_tf32(v.w);
        }
        if (!transB) {
#pragma unroll
            for (int i = tid; i < (BK * BN) / 4; i += 256) {
                int row = i / (BN / 4), nq = i % (BN / 4);
                float4 v = *(const float4*)(Bp + (long)(k0 + row) * ldb + n0 + nq * 4);
                float* dst = &sB[row * LDB + nq * 4];
                dst[0] = wmma::__float_to_tf32(v.x);
                dst[1] = wmma::__float_to_tf32(v.y);
                dst[2] = wmma::__float_to_tf32(v.z);
                dst[3] = wmma::__float_to_tf32(v.w);
            }
        } else {
#pragma unroll
            for (int i = tid; i < BK * BN; i += 256) {
                int n = i >> 5, k = i & 31;
                sB[k * LDB + n] = wmma::__float_to_tf32(Bp[(long)(n0 + n) * ldb + k0 + k]);
            }
        }
        __syncthreads();
#pragma unroll
        for (int ks = 0; ks < BK / 8; ks++) {
            wmma::fragment<wmma::matrix_a, 16, 16, 8, wmma::precision::tf32, wmma::row_major> af[MI];
            wmma::fragment<wmma::matrix_b, 16, 16, 8, wmma::precision::tf32, wmma::row_major> bf[NI];
#pragma unroll
            for (int mi = 0; mi < MI; mi++)
                wmma::load_matrix_sync(af[mi], &sA[(wm0 + mi * 16) * LDA + ks * 8], LDA);
#pragma unroll
            for (int ni = 0; ni < NI; ni++)
                wmma::load_matrix_sync(bf[ni], &sB[(ks * 8) * LDB + wn0 + ni * 16], LDB);
#pragma unroll
            for (int mi = 0; mi < MI; mi++)
#pragma unroll
                for (int ni = 0; ni < NI; ni++)
                    wmma::mma_sync(acc[mi][ni], af[mi], bf[ni], acc[mi][ni]);
        }
        __syncthreads();
    }

    // epilogue: per-warp 16x16 patches through smem
#pragma unroll
    for (int mi = 0; mi < MI; mi++) {
#pragma unroll
        for (int ni = 0; ni < NI; ni++) {
            wmma::store_matrix_sync(&cpad[wid][0], acc[mi][ni], 20, wmma::mem_row_major);
            __syncwarp();
#pragma unroll
            for (int j = 0; j < 8; j++) {
                int p = j * 32 + lane;           // 0..255
                int pr = p >> 4, pc = p & 15;
                float v = alpha * cpad[wid][pr * 20 + pc];
                int m = m0 + wm0 + mi * 16 + pr;
                int n = n0 + wn0 + ni * 16 + pc;
                if (E) v += escale * E[coff + (long)m * ldc + n];
                if (bias) v += bias[n];
                if (gelu) v = 0.5f * v * (1.0f + erff(v * 0.70710678118654752f));
                if (remap) {
                    int bI = m >> 10;            // N = 1024
                    int nn = m & 1023;
                    if (nn >= PADN)
                        C[((long)bI * L + (nn - PADN)) * ldc + n] += v;
                } else {
                    long idx = coff + (long)m * ldc + n;
                    if (accumulate) C[idx] += v; else C[idx] = v;
                }
            }
            __syncwarp();
        }
    }
}

// ------------------------- elementwise / reduction kernels -------------------
__global__ void embed_kernel(const int* __restrict__ x, const float* __restrict__ enc,
                             const float* __restrict__ pos, float* __restrict__ h) {
    long idx = (long)blockIdx.x * 256 + threadIdx.x;   // B*L*D total
    int d = (int)(idx % D);
    long bl = idx / D;
    int l = (int)(bl % L);
    h[idx] = enc[(long)x[bl] * D + d] + pos[(long)l * D + d];
}

__global__ void ln_pad_kernel(const float* __restrict__ src, float* __restrict__ dst,
                              const float* __restrict__ s, const float* __restrict__ bia) {
    int row = blockIdx.x;                 // B*N rows
    int b = row >> 10, n = row & 1023;
    int tid = threadIdx.x;                // 256 threads, 2 elems each
    float* out = dst + (long)row * D;
    if (n < PADN) { out[tid] = 0.f; out[tid + 256] = 0.f; return; }
    const float* in = src + ((long)b * L + (n - PADN)) * D;
    __shared__ float sh[33];
    float v0 = in[tid], v1 = in[tid + 256];
    float mu = blkSum(v0 + v1, sh) * (1.0f / D);
    float d0 = v0 - mu, d1 = v1 - mu;
    float var = blkSum(d0 * d0 + d1 * d1, sh) * (1.0f / D);
    float r = rsqrtf(var + 1e-5f);
    out[tid]       = d0 * r * s[tid]       + bia[tid];
    out[tid + 256] = d1 * r * s[tid + 256] + bia[tid + 256];
}

__global__ void ln_kernel(const float* __restrict__ src, float* __restrict__ dst,
                          const float* __restrict__ s, const float* __restrict__ bia) {
    long row = blockIdx.x;                // B*L rows
    int tid = threadIdx.x;
    const float* in = src + row * D;
    float* out = dst + row * D;
    __shared__ float sh[33];
    float v0 = in[tid], v1 = in[tid + 256];
    float mu = blkSum(v0 + v1, sh) * (1.0f / D);
    float d0 = v0 - mu, d1 = v1 - mu;
    float var = blkSum(d0 * d0 + d1 * d1, sh) * (1.0f / D);
    float r = rsqrtf(var + 1e-5f);
    out[tid]       = d0 * r * s[tid]       + bia[tid];
    out[tid + 256] = d1 * r * s[tid + 256] + bia[tid + 256];
}

__global__ void landmark_kernel(const float* __restrict__ qkv,
                                float* __restrict__ ql, float* __restrict__ kl) {
    int idx = blockIdx.x * 256 + threadIdx.x;    // BH*M*DH total
    int d = idx & 63;
    int m = (idx >> 6) & (M - 1);
    int bh = idx >> 14;
    int b = bh >> 3, h = bh & 7;
    const float* base = qkv + ((long)(b * N + m * 4)) * 1536 + h * 64 + d;
    float sq = 0.f, sk = 0.f;
#pragma unroll
    for (int j = 0; j < 4; j++) { sq += base[j * 1536]; sk += base[j * 1536 + 512]; }
    ql[idx] = sq * 0.25f;
    kl[idx] = sk * 0.25f;
}

template <int W>
__global__ void softmax_kernel(float* __restrict__ x) {
    constexpr int PT = W / 256;
    long base = (long)blockIdx.x * W;
    int tid = threadIdx.x;
    __shared__ float sh[33];
    float v[PT];
    float mx = -3.4e38f;
#pragma unroll
    for (int p = 0; p < PT; p++) { v[p] = x[base + tid + p * 256]; mx = fmaxf(mx, v[p]); }
    mx = blkMax(mx, sh);
    float s = 0.f;
#pragma unroll
    for (int p = 0; p < PT; p++) { v[p] = expf(v[p] - mx); s += v[p]; }
    s = blkSum(s, sh);
    float inv = 1.0f / s;
#pragma unroll
    for (int p = 0; p < PT; p++) x[base + tid + p * 256] = v[p] * inv;
}

__global__ void scal_init_kernel(float* scal) {
    if (threadIdx.x < 2) scal[threadIdx.x] = 0.f;
}

__global__ void absrowmax_kernel(const float* __restrict__ x, float* scal) {
    long base = (long)blockIdx.x * M;     // BH*M rows
    __shared__ float sh[33];
    float v = fabsf(x[base + threadIdx.x]);
    float s = blkSum(v, sh);
    if (threadIdx.x == 0)
        atomicMax((unsigned int*)&scal[0], __float_as_uint(s));
}

__global__ void abscolmax_kernel(const float* __restrict__ x, float* scal) {
    const float* p = x + (long)blockIdx.x * M * M;   // BH batches
    int j = threadIdx.x;
    float s = 0.f;
    for (int i = 0; i < M; i++) s += fabsf(p[i * M + j]);
    __shared__ float sh[33];
    float m = blkMax(s, sh);
    if (threadIdx.x == 0)
        atomicMax((unsigned int*)&scal[1], __float_as_uint(m));
}

__global__ void zinit_kernel(const float* __restrict__ x, const float* __restrict__ scal,
                             float* __restrict__ z) {
    long idx = (long)blockIdx.x * 256 + threadIdx.x;  // BH*M*M
    float inv = 1.0f / (scal[0] * scal[1]);
    int j = (int)(idx & 255);
    int i = (int)((idx >> 8) & 255);
    long bh = idx >> 16;
    z[idx] = x[(bh << 16) + (long)j * M + i] * inv;
}

__global__ void conv_kernel(const float* __restrict__ qkv, const float* __restrict__ ck,
                            float* __restrict__ ctx) {
    __shared__ float sv[160 * 64];
    __shared__ float sck[KC];
    int bh = blockIdx.y;
    int b = bh >> 3, h = bh & 7;
    int n0 = blockIdx.x * 128;
    int tid = threadIdx.x;
    if (tid < KC) sck[tid] = ck[h * KC + tid];
    for (int i = tid; i < 160 * 64; i += 256) {
        int r = i >> 6, d = i & 63;
        int n = n0 - 16 + r;
        float v = 0.f;
        if (n >= 0 && n < N) v = qkv[((long)(b * N + n)) * 1536 + 1024 + h * 64 + d];
        sv[i] = v;
    }
    __syncthreads();
    for (int o = tid; o < 128 * 64; o += 256) {
        int nl = o >> 6, d = o & 63;
        float s = 0.f;
#pragma unroll
        for (int t = 0; t < KC; t++) s += sck[t] * sv[(nl + t) * 64 + d];
        ctx[((long)(b * N + n0 + nl)) * D + h * 64 + d] = s;
    }
}

__global__ void final_partial_kernel(const float* __restrict__ h, const float* __restrict__ fw,
                                     float* __restrict__ part) {
    int b = blockIdx.y, c = blockIdx.x;   // 64 chunks per batch
    const int CHK = (L * D) / 64;         // 8000
    long base = (long)b * L * D;
    float s = 0.f;
    for (int i = c * CHK + threadIdx.x; i < (c + 1) * CHK; i += 256)
        s += h[base + i] * fw[i];
    __shared__ float sh[33];
    s = blkSum(s, sh);
    if (threadIdx.x == 0) part[b * 64 + c] = s;
}

__global__ void final_reduce_kernel(const float* __restrict__ part, const float* __restrict__ fb,
                                    float* __restrict__ out) {
    int b = blockIdx.x;
    int t = threadIdx.x;  // 32
    float v = part[b * 64 + t] + part[b * 64 + t + 32];
#pragma unroll
    for (int o = 16; o; o >>= 1) v += __shfl_xor_sync(0xffffffffu, v, o);
    if (t == 0) out[b] = v + fb[0];
}

} // namespace nys

// ------------------------- host orchestration --------------------------------
static float* nys_sym(const void* s) {
    void* p = nullptr;
    cudaGetSymbolAddress(&p, s);
    return (float*)p;
}

static void gemm(int cfg128, int Mdim, int Ndim, int K,
                 const float* A, int lda, long sA1, long sA2,
                 const float* Bm, int ldb, long sB1, long sB2, int tB,
                 float* C, int ldc, long sC1, long sC2,
                 int batch, int Hd, float alpha,
                 const float* bias, int gelu, const float* E, float es,
                 int acc, int remap) {
    if (cfg128) {
        dim3 g(Ndim / 128, Mdim / 128, batch);
        nys::tgemm<128, 128, 32, 64><<<g, 256>>>(K, A, lda, sA1, sA2, Bm, ldb, sB1, sB2, tB,
                                                 C, ldc, sC1, sC2, Hd, alpha, bias, gelu, E, es, acc, remap);
    } else {
        dim3 g(Ndim / 64, Mdim / 64, batch);
        nys::tgemm<64, 64, 16, 32><<<g, 256>>>(K, A, lda, sA1, sA2, Bm, ldb, sB1, sB2, tB,
                                               C, ldc, sC1, sC2, Hd, alpha, bias, gelu, E, es, acc, remap);
    }
}

extern "C" void kernel_launch(void* const* d_in, const int* in_sizes, int n_in,
                              void* d_out, int out_size) {
    using namespace nys;
    (void)in_sizes; (void)n_in; (void)out_size;

    const int*   xin    = (const int*)  d_in[0];
    const float* enc    = (const float*)d_in[1];
    const float* pos    = (const float*)d_in[2];
    const float* ln1_s  = (const float*)d_in[3];
    const float* ln1_b  = (const float*)d_in[4];
    const float* qkv_w  = (const float*)d_in[5];
    const float* out_w  = (const float*)d_in[6];
    const float* out_b  = (const float*)d_in[7];
    const float* conv_k = (const float*)d_in[8];
    const float* ln2_s  = (const float*)d_in[9];
    const float* ln2_b  = (const float*)d_in[10];
    const float* ff_w1  = (const float*)d_in[11];
    const float* ff_b1  = (const float*)d_in[12];
    const float* ff_w2  = (const float*)d_in[13];
    const float* ff_b2  = (const float*)d_in[14];
    const float* fin_w  = (const float*)d_in[15];
    const float* fin_b  = (const float*)d_in[16];
    float* out = (float*)d_out;

    float* h     = nys_sym(g_h);
    float* xp    = nys_sym(g_xp);
    float* x2    = nys_sym(g_x2);
    float* qkv   = nys_sym(g_qkv);
    float* ql    = nys_sym(g_ql);
    float* kl    = nys_sym(g_kl);
    float* attn1 = nys_sym(g_attn1);
    float* attn3 = nys_sym(g_attn3);
    float* attn2 = nys_sym(g_attn2);
    float* zb    = nys_sym(g_z);
    float* zb2   = nys_sym(g_z2);
    float* xz    = nys_sym(g_xz);
    float* u1    = nys_sym(g_u1);
    float* u3    = nys_sym(g_u3);
    float* av    = nys_sym(g_av);
    float* tt    = nys_sym(g_t);
    float* ctx   = nys_sym(g_ctx);
    float* ff    = nys_sym(g_ff);
    float* scal  = nys_sym(g_scal);
    float* part  = nys_sym(g_part);

    const long MM2 = (long)M * M;

    embed_kernel<<<(B * L * D) / 256, 256>>>(xin, enc, pos, h);

    for (int i = 0; i < DEPTH; i++) {
        const float* qw  = qkv_w  + (long)i * D * 3 * D;
        const float* ow  = out_w  + (long)i * D * D;
        const float* ob  = out_b  + (long)i * D;
        const float* ckp = conv_k + (long)i * H * KC;
        const float* w1  = ff_w1  + (long)i * D * FF;
        const float* b1  = ff_b1  + (long)i * FF;
        const float* w2  = ff_w2  + (long)i * FF * D;
        const float* b2  = ff_b2  + (long)i * D;

        // LN1 + left-pad into xp (B*N rows)
        ln_pad_kernel<<<B * N, 256>>>(h, xp, ln1_s + (long)i * D, ln1_b + (long)i * D);

        // qkv = xp @ qkv_w   (16384 x 1536 x 512)
        gemm(1, B * N, 3 * D, D, xp, D, 0, 0, qw, 3 * D, 0, 0, 0,
             qkv, 3 * D, 0, 0, 1, 1, 1.f, nullptr, 0, nullptr, 0.f, 0, 0);

        // landmark means (q_l unscaled; SCALE folded into logit alphas)
        landmark_kernel<<<(BH * M * DH) / 256, 256>>>(qkv, ql, kl);

        // attn1 = softmax(SCALE * q @ k_l^T)   (1024 x 256 x 64, batched bh)
        gemm(1, N, M, DH,
             qkv, 3 * D, (long)N * 3 * D, 64,
             kl, DH, (long)H * M * DH, (long)M * DH, 1,
             attn1, M, (long)H * N * M, (long)N * M,
             BH, H, SCALE, nullptr, 0, nullptr, 0.f, 0, 0);
        softmax_kernel<256><<<BH * N, 256>>>(attn1);

        // attn2 = softmax(SCALE * q_l @ k_l^T) (256 x 256 x 64)
        gemm(1, M, M, DH,
             ql, DH, (long)H * M * DH, (long)M * DH,
             kl, DH, (long)H * M * DH, (long)M * DH, 1,
             attn2, M, (long)H * M * M, MM2,
             BH, H, SCALE, nullptr, 0, nullptr, 0.f, 0, 0);
        softmax_kernel<256><<<BH * M, 256>>>(attn2);

        // attn3 = softmax(SCALE * q_l @ k^T)   (256 x 1024 x 64)
        gemm(1, M, N, DH,
             ql, DH, (long)H * M * DH, (long)M * DH,
             qkv + D, 3 * D, (long)N * 3 * D, 64, 1,
             attn3, N, (long)H * M * N, (long)M * N,
             BH, H, SCALE, nullptr, 0, nullptr, 0.f, 0, 0);
        softmax_kernel<1024><<<BH * M, 256>>>(attn3);

        // Moore-Penrose pinv of attn2 (6 iterations)
        scal_init_kernel<<<1, 32>>>(scal);
        absrowmax_kernel<<<BH * M, 256>>>(attn2, scal);
        abscolmax_kernel<<<BH, 256>>>(attn2, scal);
        zinit_kernel<<<(BH * M * M) / 256, 256>>>(attn2, scal, zb);

        float* zc = zb;
        float* zn = zb2;
        for (int it = 0; it < 6; it++) {
            // xz = x @ z
            gemm(1, M, M, M, attn2, M, MM2, 0, zc, M, MM2, 0, 0,
                 xz, M, MM2, 0, BH, 1, 1.f, nullptr, 0, nullptr, 0.f, 0, 0);
            // u1 = 7*xz - xz@xz
            gemm(1, M, M, M, xz, M, MM2, 0, xz, M, MM2, 0, 0,
                 u1, M, MM2, 0, BH, 1, -1.f, nullptr, 0, xz, 7.f, 0, 0);
            // u3 = 15*xz - xz@u1
            gemm(1, M, M, M, xz, M, MM2, 0, u1, M, MM2, 0, 0,
                 u3, M, MM2, 0, BH, 1, -1.f, nullptr, 0, xz, 15.f, 0, 0);
            // z' = 3.25*z - 0.25*z@u3
            gemm(1, M, M, M, zc, M, MM2, 0, u3, M, MM2, 0, 0,
                 zn, M, MM2, 0, BH, 1, -0.25f, nullptr, 0, zc, 3.25f, 0, 0);
            float* tmp = zc; zc = zn; zn = tmp;
        }
        // zc holds pinv(attn2) after 6 iterations

        // av = attn3 @ v    (256 x 64 x 1024)
        gemm(0, M, DH, N,
             attn3, N, (long)H * M * N, (long)M * N,
             qkv + 2 * D, 3 * D, (long)N * 3 * D, 64, 0,
             av, DH, (long)H * M * DH, (long)M * DH,
             BH, H, 1.f, nullptr, 0, nullptr, 0.f, 0, 0);

        // conv residual into ctx (B,N,D layout)
        conv_kernel<<<dim3(N / 128, BH), 256>>>(qkv, ckp, ctx);

        // t = attn1 @ pinv  (1024 x 256 x 256)
        gemm(1, N, M, M,
             attn1, M, (long)N * M, 0,
             zc, M, MM2, 0, 0,
             tt, M, (long)N * M, 0,
             BH, 1, 1.f, nullptr, 0, nullptr, 0.f, 0, 0);

        // ctx += t @ av     (1024 x 64 x 256), strided write into (B,N,D)
        gemm(0, N, DH, M,
             tt, M, (long)H * N * M, (long)N * M,
             av, DH, (long)H * M * DH, (long)M * DH, 0,
             ctx, D, (long)N * D, 64,
             BH, H, 1.f, nullptr, 0, nullptr, 0.f, 1, 0);

        // h += (ctx @ out_w + out_b)[:, -L:]   (remap epilogue)
        gemm(1, B * N, D, D, ctx, D, 0, 0, ow, D, 0, 0, 0,
             h, D, 0, 0, 1, 1, 1.f, ob, 0, nullptr, 0.f, 0, 1);

        // FFN
        ln_kernel<<<B * L, 256>>>(h, x2, ln2_s + (long)i * D, ln2_b + (long)i * D);
        gemm(1, B * L, FF, D, x2, D, 0, 0, w1, FF, 0, 0, 0,
             ff, FF, 0, 0, 1, 1, 1.f, b1, 1, nullptr, 0.f, 0, 0);
        gemm(1, B * L, D, FF, ff, FF, 0, 0, w2, D, 0, 0, 0,
             h, D, 0, 0, 1, 1, 1.f, b2, 0, nullptr, 0.f, 1, 0);
    }

    final_partial_kernel<<<dim3(64, B), 256>>>(h, fin_w, part);
    final_reduce_kernel<<<B, 32>>>(part, fin_b, out);
}

// round 4
// speedup vs baseline: 1.6391x; 1.2598x over previous
#include <cuda_runtime.h>
#include <cstdint>
#include <math.h>
#include <mma.h>

using namespace nvcuda;

namespace nys {

constexpr int B = 16, L = 1000, D = 512, H = 8, DH = 64;
constexpr int N = 1024, M = 256, PADN = 24, DEPTH = 6, FF = 2048, KC = 33;
constexpr int BH = B * H;
constexpr float SCALE = 0.125f;   // DH^-0.5

// ------------------------- scratch (static device memory) -------------------
__device__ float g_h   [B * L * D];
__device__ float g_xp  [B * N * D];
__device__ float g_x2  [B * L * D];
__device__ float g_qkv [B * N * 3 * D];
__device__ float g_ql  [BH * M * DH];
__device__ float g_kl  [BH * M * DH];
__device__ float g_attn1[BH * N * M];
__device__ float g_attn3[BH * M * N];
__device__ float g_attn2[BH * M * M];
__device__ float g_z   [BH * M * M];
__device__ float g_z2  [BH * M * M];
__device__ float g_xz  [BH * M * M];
__device__ float g_u1  [BH * M * M];
__device__ float g_u3  [BH * M * M];
__device__ float g_av  [BH * M * DH];
__device__ float g_t   [BH * N * M];
__device__ float g_ctx [B * N * D];
__device__ float g_ff  [B * L * FF];
__device__ float g_scal[2];
__device__ float g_part[B * 64];

// ------------------------- cp.async helpers ---------------------------------
__device__ __forceinline__ void cpa16(void* s, const void* g) {
    unsigned int sa = (unsigned int)__cvta_generic_to_shared(s);
    asm volatile("cp.async.ca.shared.global [%0], [%1], 16;\n" :: "r"(sa), "l"(g));
}
__device__ __forceinline__ void cpa4(void* s, const void* g) {
    unsigned int sa = (unsigned int)__cvta_generic_to_shared(s);
    asm volatile("cp.async.ca.shared.global [%0], [%1], 4;\n" :: "r"(sa), "l"(g));
}
__device__ __forceinline__ void cpa_commit() {
    asm volatile("cp.async.commit_group;\n" ::: "memory");
}
__device__ __forceinline__ void cpa_waitall() {
    asm volatile("cp.async.wait_group 0;\n" ::: "memory");
}

// ------------------------- block reduction helpers --------------------------
__device__ __forceinline__ float blkSum(float v, float* sh) {
    int lane = threadIdx.x & 31, w = threadIdx.x >> 5;
#pragma unroll
    for (int o = 16; o; o >>= 1) v += __shfl_xor_sync(0xffffffffu, v, o);
    if (lane == 0) sh[w] = v;
    __syncthreads();
    if (w == 0) {
        float t = (lane < (int)(blockDim.x >> 5)) ? sh[lane] : 0.f;
#pragma unroll
        for (int o = 16; o; o >>= 1) t += __shfl_xor_sync(0xffffffffu, t, o);
        if (lane == 0) sh[32] = t;
    }
    __syncthreads();
    float r = sh[32];
    __syncthreads();
    return r;
}

__device__ __forceinline__ float blkMax(float v, float* sh) {
    int lane = threadIdx.x & 31, w = threadIdx.x >> 5;
#pragma unroll
    for (int o = 16; o; o >>= 1) v = fmaxf(v, __shfl_xor_sync(0xffffffffu, v, o));
    if (lane == 0) sh[w] = v;
    __syncthreads();
    if (w == 0) {
        float t = (lane < (int)(blockDim.x >> 5)) ? sh[lane] : -3.4e38f;
#pragma unroll
        for (int o = 16; o; o >>= 1) t = fmaxf(t, __shfl_xor_sync(0xffffffffu, t, o));
        if (lane == 0) sh[32] = t;
    }
    __syncthreads();
    float r = sh[32];
    __syncthreads();
    return r;
}

// ------------------------- tf32 tensor-core batched GEMM ---------------------
// C = alpha * A(@/@T)B  [+ escale*E] [+ bias] [gelu] [accumulate / row-remap]
// A fp32 row-major [m,k]; B fp32 row-major [k,n] (transB=0) or [n,k] (transB=1).
// Raw fp32 fed to tf32 mma (hardware mantissa truncation). fp32 accumulate.
// 128 threads, 4 warps, double-buffered cp.async pipeline, BK=32.
template <int BM, int BN, int WM, int WN>
__global__ void __launch_bounds__(128) tgemm(
    int Kdim,
    const float* __restrict__ A, int lda, long sA1, long sA2,
    const float* __restrict__ Bm, int ldb, long sB1, long sB2, int transB,
    float* __restrict__ C, int ldc, long sC1, long sC2,
    int Hd, float alpha,
    const float* __restrict__ bias, int gelu,
    const float* __restrict__ E, float escale,
    int accumulate, int remap)
{
    constexpr int BK   = 32;
    constexpr int LDA  = BK + 4;      // 36
    constexpr int LDB  = BN + 4;
    constexpr int MI   = WM / 16;
    constexpr int NI   = WN / 16;
    constexpr int WCOL = BN / WN;     // warps along n
    constexpr int NWARP = (BM / WM) * (BN / WN);
    static_assert(NWARP == 4, "4 warps");

    extern __shared__ float smem[];
    float* sA0 = smem;                  // 2 * BM * LDA
    float* sB0 = smem + 2 * BM * LDA;   // 2 * BK * LDB

    int tid = threadIdx.x;
    int wid = tid >> 5, lane = tid & 31;
    int m0 = blockIdx.y * BM, n0 = blockIdx.x * BN;
    int z = blockIdx.z;
    int bb = z / Hd, hh = z - bb * Hd;
    const float* Ap = A + (long)bb * sA1 + (long)hh * sA2;
    const float* Bp = Bm + (long)bb * sB1 + (long)hh * sB2;
    long coff = (long)bb * sC1 + (long)hh * sC2;

    int wm0 = (wid / WCOL) * WM;
    int wn0 = (wid % WCOL) * WN;

    wmma::fragment<wmma::accumulator, 16, 16, 8, float> acc[MI][NI];
#pragma unroll
    for (int mi = 0; mi < MI; mi++)
#pragma unroll
        for (int ni = 0; ni < NI; ni++) wmma::fill_fragment(acc[mi][ni], 0.f);

    auto stage = [&](int bf, int k0) {
        float* sA = sA0 + bf * (BM * LDA);
        float* sB = sB0 + bf * (BK * LDB);
#pragma unroll
        for (int t = 0; t < (BM * BK) / (4 * 128); t++) {
            int i = t * 128 + tid;
            int row = i / (BK / 4), kq = i % (BK / 4);
            cpa16(&sA[row * LDA + kq * 4], Ap + (long)(m0 + row) * lda + k0 + kq * 4);
        }
        if (!transB) {
#pragma unroll
            for (int t = 0; t < (BK * BN) / (4 * 128); t++) {
                int i = t * 128 + tid;
                int row = i / (BN / 4), nq = i % (BN / 4);
                cpa16(&sB[row * LDB + nq * 4], Bp + (long)(k0 + row) * ldb + n0 + nq * 4);
            }
        } else {
#pragma unroll
            for (int t = 0; t < (BK * BN) / 128; t++) {
                int i = t * 128 + tid;
                int n = i >> 5, k = i & 31;
                cpa4(&sB[k * LDB + n], Bp + (long)(n0 + n) * ldb + k0 + k);
            }
        }
    };

    stage(0, 0);
    cpa_commit();
    int buf = 0;

    for (int k0 = 0; k0 < Kdim; k0 += BK) {
        cpa_waitall();
        __syncthreads();
        if (k0 + BK < Kdim) { stage(buf ^ 1, k0 + BK); cpa_commit(); }

        const float* cA = sA0 + buf * (BM * LDA);
        const float* cB = sB0 + buf * (BK * LDB);
#pragma unroll
        for (int ks = 0; ks < BK / 8; ks++) {
            wmma::fragment<wmma::matrix_a, 16, 16, 8, wmma::precision::tf32, wmma::row_major> af[MI];
            wmma::fragment<wmma::matrix_b, 16, 16, 8, wmma::precision::tf32, wmma::row_major> bf[NI];
#pragma unroll
            for (int mi = 0; mi < MI; mi++)
                wmma::load_matrix_sync(af[mi], &cA[(wm0 + mi * 16) * LDA + ks * 8], LDA);
#pragma unroll
            for (int ni = 0; ni < NI; ni++)
                wmma::load_matrix_sync(bf[ni], &cB[(ks * 8) * LDB + wn0 + ni * 16], LDB);
#pragma unroll
            for (int mi = 0; mi < MI; mi++)
#pragma unroll
                for (int ni = 0; ni < NI; ni++)
                    wmma::mma_sync(acc[mi][ni], af[mi], bf[ni], acc[mi][ni]);
        }
        __syncthreads();
        buf ^= 1;
    }

    // epilogue: per-warp 16x16 patches staged through smem (reuse sA region)
    float* cpad = smem + wid * (16 * 20);
#pragma unroll
    for (int mi = 0; mi < MI; mi++) {
#pragma unroll
        for (int ni = 0; ni < NI; ni++) {
            wmma::store_matrix_sync(cpad, acc[mi][ni], 20, wmma::mem_row_major);
            __syncwarp();
#pragma unroll
            for (int j = 0; j < 8; j++) {
                int p = j * 32 + lane;           // 0..255
                int pr = p >> 4, pc = p & 15;
                float v = alpha * cpad[pr * 20 + pc];
                int m = m0 + wm0 + mi * 16 + pr;
                int n = n0 + wn0 + ni * 16 + pc;
                if (E) v += escale * E[coff + (long)m * ldc + n];
                if (bias) v += bias[n];
                if (gelu) v = 0.5f * v * (1.0f + erff(v * 0.70710678118654752f));
                if (remap) {
                    int bI = m >> 10;            // N = 1024
                    int nn = m & 1023;
                    if (nn >= PADN)
                        C[((long)bI * L + (nn - PADN)) * ldc + n] += v;
                } else {
                    long idx = coff + (long)m * ldc + n;
                    if (accumulate) C[idx] += v; else C[idx] = v;
                }
            }
            __syncwarp();
        }
    }
}

// ------------------------- elementwise / reduction kernels -------------------
__global__ void embed_kernel(const int* __restrict__ x, const float* __restrict__ enc,
                             const float* __restrict__ pos, float* __restrict__ h) {
    long idx = (long)blockIdx.x * 256 + threadIdx.x;   // B*L*D total
    int d = (int)(idx % D);
    long bl = idx / D;
    int l = (int)(bl % L);
    h[idx] = enc[(long)x[bl] * D + d] + pos[(long)l * D + d];
}

__global__ void ln_pad_kernel(const float* __restrict__ src, float* __restrict__ dst,
                              const float* __restrict__ s, const float* __restrict__ bia) {
    int row = blockIdx.x;                 // B*N rows
    int b = row >> 10, n = row & 1023;
    int tid = threadIdx.x;                // 256 threads, 2 elems each
    float* out = dst + (long)row * D;
    if (n < PADN) { out[tid] = 0.f; out[tid + 256] = 0.f; return; }
    const float* in = src + ((long)b * L + (n - PADN)) * D;
    __shared__ float sh[33];
    float v0 = in[tid], v1 = in[tid + 256];
    float mu = blkSum(v0 + v1, sh) * (1.0f / D);
    float d0 = v0 - mu, d1 = v1 - mu;
    float var = blkSum(d0 * d0 + d1 * d1, sh) * (1.0f / D);
    float r = rsqrtf(var + 1e-5f);
    out[tid]       = d0 * r * s[tid]       + bia[tid];
    out[tid + 256] = d1 * r * s[tid + 256] + bia[tid + 256];
}

__global__ void ln_kernel(const float* __restrict__ src, float* __restrict__ dst,
                          const float* __restrict__ s, const float* __restrict__ bia) {
    long row = blockIdx.x;                // B*L rows
    int tid = threadIdx.x;
    const float* in = src + row * D;
    float* out = dst + row * D;
    __shared__ float sh[33];
    float v0 = in[tid], v1 = in[tid + 256];
    float mu = blkSum(v0 + v1, sh) * (1.0f / D);
    float d0 = v0 - mu, d1 = v1 - mu;
    float var = blkSum(d0 * d0 + d1 * d1, sh) * (1.0f / D);
    float r = rsqrtf(var + 1e-5f);
    out[tid]       = d0 * r * s[tid]       + bia[tid];
    out[tid + 256] = d1 * r * s[tid + 256] + bia[tid + 256];
}

__global__ void landmark_kernel(const float* __restrict__ qkv,
                                float* __restrict__ ql, float* __restrict__ kl) {
    int idx = blockIdx.x * 256 + threadIdx.x;    // BH*M*DH total
    int d = idx & 63;
    int m = (idx >> 6) & (M - 1);
    int bh = idx >> 14;
    int b = bh >> 3, h = bh & 7;
    const float* base = qkv + ((long)(b * N + m * 4)) * 1536 + h * 64 + d;
    float sq = 0.f, sk = 0.f;
#pragma unroll
    for (int j = 0; j < 4; j++) { sq += base[j * 1536]; sk += base[j * 1536 + 512]; }
    ql[idx] = sq * 0.25f;
    kl[idx] = sk * 0.25f;
}

template <int W>
__global__ void softmax_kernel(float* __restrict__ x) {
    constexpr int PT = W / 256;
    long base = (long)blockIdx.x * W;
    int tid = threadIdx.x;
    __shared__ float sh[33];
    float v[PT];
    float mx = -3.4e38f;
#pragma unroll
    for (int p = 0; p < PT; p++) { v[p] = x[base + tid + p * 256]; mx = fmaxf(mx, v[p]); }
    mx = blkMax(mx, sh);
    float s = 0.f;
#pragma unroll
    for (int p = 0; p < PT; p++) { v[p] = expf(v[p] - mx); s += v[p]; }
    s = blkSum(s, sh);
    float inv = 1.0f / s;
#pragma unroll
    for (int p = 0; p < PT; p++) x[base + tid + p * 256] = v[p] * inv;
}

__global__ void scal_init_kernel(float* scal) {
    if (threadIdx.x < 2) scal[threadIdx.x] = 0.f;
}

__global__ void absrowmax_kernel(const float* __restrict__ x, float* scal) {
    long base = (long)blockIdx.x * M;     // BH*M rows
    __shared__ float sh[33];
    float v = fabsf(x[base + threadIdx.x]);
    float s = blkSum(v, sh);
    if (threadIdx.x == 0)
        atomicMax((unsigned int*)&scal[0], __float_as_uint(s));
}

__global__ void abscolmax_kernel(const float* __restrict__ x, float* scal) {
    const float* p = x + (long)blockIdx.x * M * M;   // BH batches
    int j = threadIdx.x;
    float s = 0.f;
    for (int i = 0; i < M; i++) s += fabsf(p[i * M + j]);
    __shared__ float sh[33];
    float m = blkMax(s, sh);
    if (threadIdx.x == 0)
        atomicMax((unsigned int*)&scal[1], __float_as_uint(m));
}

__global__ void zinit_kernel(const float* __restrict__ x, const float* __restrict__ scal,
                             float* __restrict__ z) {
    long idx = (long)blockIdx.x * 256 + threadIdx.x;  // BH*M*M
    float inv = 1.0f / (scal[0] * scal[1]);
    int j = (int)(idx & 255);
    int i = (int)((idx >> 8) & 255);
    long bh = idx >> 16;
    z[idx] = x[(bh << 16) + (long)j * M + i] * inv;
}

__global__ void conv_kernel(const float* __restrict__ qkv, const float* __restrict__ ck,
                            float* __restrict__ ctx) {
    __shared__ float sv[160 * 64];
    __shared__ float sck[KC];
    int bh = blockIdx.y;
    int b = bh >> 3, h = bh & 7;
    int n0 = blockIdx.x * 128;
    int tid = threadIdx.x;
    if (tid < KC) sck[tid] = ck[h * KC + tid];
    for (int i = tid; i < 160 * 64; i += 256) {
        int r = i >> 6, d = i & 63;
        int n = n0 - 16 + r;
        float v = 0.f;
        if (n >= 0 && n < N) v = qkv[((long)(b * N + n)) * 1536 + 1024 + h * 64 + d];
        sv[i] = v;
    }
    __syncthreads();
    for (int o = tid; o < 128 * 64; o += 256) {
        int nl = o >> 6, d = o & 63;
        float s = 0.f;
#pragma unroll
        for (int t = 0; t < KC; t++) s += sck[t] * sv[(nl + t) * 64 + d];
        ctx[((long)(b * N + n0 + nl)) * D + h * 64 + d] = s;
    }
}

__global__ void final_partial_kernel(const float* __restrict__ h, const float* __restrict__ fw,
                                     float* __restrict__ part) {
    int b = blockIdx.y, c = blockIdx.x;   // 64 chunks per batch
    const int CHK = (L * D) / 64;         // 8000
    long base = (long)b * L * D;
    float s = 0.f;
    for (int i = c * CHK + threadIdx.x; i < (c + 1) * CHK; i += 256)
        s += h[base + i] * fw[i];
    __shared__ float sh[33];
    s = blkSum(s, sh);
    if (threadIdx.x == 0) part[b * 64 + c] = s;
}

__global__ void final_reduce_kernel(const float* __restrict__ part, const float* __restrict__ fb,
                                    float* __restrict__ out) {
    int b = blockIdx.x;
    int t = threadIdx.x;  // 32
    float v = part[b * 64 + t] + part[b * 64 + t + 32];
#pragma unroll
    for (int o = 16; o; o >>= 1) v += __shfl_xor_sync(0xffffffffu, v, o);
    if (t == 0) out[b] = v + fb[0];
}

} // namespace nys

// ------------------------- host orchestration --------------------------------
static float* nys_sym(const void* s) {
    void* p = nullptr;
    cudaGetSymbolAddress(&p, s);
    return (float*)p;
}

static constexpr size_t SMEM128 = (size_t)(2 * (128 * 36) + 2 * (32 * 132)) * 4;  // 70656
static constexpr size_t SMEM64  = (size_t)(2 * (128 * 36) + 2 * (32 * 68))  * 4;  // 54272

static void gemm(int cfg128, int Mdim, int Ndim, int K,
                 const float* A, int lda, long sA1, long sA2,
                 const float* Bm, int ldb, long sB1, long sB2, int tB,
                 float* C, int ldc, long sC1, long sC2,
                 int batch, int Hd, float alpha,
                 const float* bias, int gelu, const float* E, float es,
                 int acc, int remap) {
    if (cfg128) {
        cudaFuncSetAttribute(nys::tgemm<128, 128, 64, 64>,
                             cudaFuncAttributeMaxDynamicSharedMemorySize, (int)SMEM128);
        dim3 g(Ndim / 128, Mdim / 128, batch);
        nys::tgemm<128, 128, 64, 64><<<g, 128, SMEM128>>>(
            K, A, lda, sA1, sA2, Bm, ldb, sB1, sB2, tB,
            C, ldc, sC1, sC2, Hd, alpha, bias, gelu, E, es, acc, remap);
    } else {
        cudaFuncSetAttribute(nys::tgemm<128, 64, 64, 32>,
                             cudaFuncAttributeMaxDynamicSharedMemorySize, (int)SMEM64);
        dim3 g(Ndim / 64, Mdim / 128, batch);
        nys::tgemm<128, 64, 64, 32><<<g, 128, SMEM64>>>(
            K, A, lda, sA1, sA2, Bm, ldb, sB1, sB2, tB,
            C, ldc, sC1, sC2, Hd, alpha, bias, gelu, E, es, acc, remap);
    }
}

extern "C" void kernel_launch(void* const* d_in, const int* in_sizes, int n_in,
                              void* d_out, int out_size) {
    using namespace nys;
    (void)in_sizes; (void)n_in; (void)out_size;

    const int*   xin    = (const int*)  d_in[0];
    const float* enc    = (const float*)d_in[1];
    const float* pos    = (const float*)d_in[2];
    const float* ln1_s  = (const float*)d_in[3];
    const float* ln1_b  = (const float*)d_in[4];
    const float* qkv_w  = (const float*)d_in[5];
    const float* out_w  = (const float*)d_in[6];
    const float* out_b  = (const float*)d_in[7];
    const float* conv_k = (const float*)d_in[8];
    const float* ln2_s  = (const float*)d_in[9];
    const float* ln2_b  = (const float*)d_in[10];
    const float* ff_w1  = (const float*)d_in[11];
    const float* ff_b1  = (const float*)d_in[12];
    const float* ff_w2  = (const float*)d_in[13];
    const float* ff_b2  = (const float*)d_in[14];
    const float* fin_w  = (const float*)d_in[15];
    const float* fin_b  = (const float*)d_in[16];
    float* out = (float*)d_out;

    float* h     = nys_sym(g_h);
    float* xp    = nys_sym(g_xp);
    float* x2    = nys_sym(g_x2);
    float* qkv   = nys_sym(g_qkv);
    float* ql    = nys_sym(g_ql);
    float* kl    = nys_sym(g_kl);
    float* attn1 = nys_sym(g_attn1);
    float* attn3 = nys_sym(g_attn3);
    float* attn2 = nys_sym(g_attn2);
    float* zb    = nys_sym(g_z);
    float* zb2   = nys_sym(g_z2);
    float* xz    = nys_sym(g_xz);
    float* u1    = nys_sym(g_u1);
    float* u3    = nys_sym(g_u3);
    float* av    = nys_sym(g_av);
    float* tt    = nys_sym(g_t);
    float* ctx   = nys_sym(g_ctx);
    float* ff    = nys_sym(g_ff);
    float* scal  = nys_sym(g_scal);
    float* part  = nys_sym(g_part);

    const long MM2 = (long)M * M;

    embed_kernel<<<(B * L * D) / 256, 256>>>(xin, enc, pos, h);

    for (int i = 0; i < DEPTH; i++) {
        const float* qw  = qkv_w  + (long)i * D * 3 * D;
        const float* ow  = out_w  + (long)i * D * D;
        const float* ob  = out_b  + (long)i * D;
        const float* ckp = conv_k + (long)i * H * KC;
        const float* w1  = ff_w1  + (long)i * D * FF;
        const float* b1  = ff_b1  + (long)i * FF;
        const float* w2  = ff_w2  + (long)i * FF * D;
        const float* b2  = ff_b2  + (long)i * D;

        // LN1 + left-pad into xp (B*N rows)
        ln_pad_kernel<<<B * N, 256>>>(h, xp, ln1_s + (long)i * D, ln1_b + (long)i * D);

        // qkv = xp @ qkv_w   (16384 x 1536 x 512)
        gemm(1, B * N, 3 * D, D, xp, D, 0, 0, qw, 3 * D, 0, 0, 0,
             qkv, 3 * D, 0, 0, 1, 1, 1.f, nullptr, 0, nullptr, 0.f, 0, 0);

        // landmark means (q_l unscaled; SCALE folded into logit alphas)
        landmark_kernel<<<(BH * M * DH) / 256, 256>>>(qkv, ql, kl);

        // attn1 = softmax(SCALE * q @ k_l^T)   (1024 x 256 x 64, batched bh)
        gemm(1, N, M, DH,
             qkv, 3 * D, (long)N * 3 * D, 64,
             kl, DH, (long)H * M * DH, (long)M * DH, 1,
             attn1, M, (long)H * N * M, (long)N * M,
             BH, H, SCALE, nullptr, 0, nullptr, 0.f, 0, 0);
        softmax_kernel<256><<<BH * N, 256>>>(attn1);

        // attn2 = softmax(SCALE * q_l @ k_l^T) (256 x 256 x 64)
        gemm(1, M, M, DH,
             ql, DH, (long)H * M * DH, (long)M * DH,
             kl, DH, (long)H * M * DH, (long)M * DH, 1,
             attn2, M, (long)H * M * M, MM2,
             BH, H, SCALE, nullptr, 0, nullptr, 0.f, 0, 0);
        softmax_kernel<256><<<BH * M, 256>>>(attn2);

        // attn3 = softmax(SCALE * q_l @ k^T)   (256 x 1024 x 64)
        gemm(1, M, N, DH,
             ql, DH, (long)H * M * DH, (long)M * DH,
             qkv + D, 3 * D, (long)N * 3 * D, 64, 1,
             attn3, N, (long)H * M * N, (long)M * N,
             BH, H, SCALE, nullptr, 0, nullptr, 0.f, 0, 0);
        softmax_kernel<1024><<<BH * M, 256>>>(attn3);

        // Moore-Penrose pinv of attn2 (6 iterations)
        scal_init_kernel<<<1, 32>>>(scal);
        absrowmax_kernel<<<BH * M, 256>>>(attn2, scal);
        abscolmax_kernel<<<BH, 256>>>(attn2, scal);
        zinit_kernel<<<(BH * M * M) / 256, 256>>>(attn2, scal, zb);

        float* zc = zb;
        float* zn = zb2;
        for (int it = 0; it < 6; it++) {
            // xz = x @ z
            gemm(1, M, M, M, attn2, M, MM2, 0, zc, M, MM2, 0, 0,
                 xz, M, MM2, 0, BH, 1, 1.f, nullptr, 0, nullptr, 0.f, 0, 0);
            // u1 = 7*xz - xz@xz
            gemm(1, M, M, M, xz, M, MM2, 0, xz, M, MM2, 0, 0,
                 u1, M, MM2, 0, BH, 1, -1.f, nullptr, 0, xz, 7.f, 0, 0);
            // u3 = 15*xz - xz@u1
            gemm(1, M, M, M, xz, M, MM2, 0, u1, M, MM2, 0, 0,
                 u3, M, MM2, 0, BH, 1, -1.f, nullptr, 0, xz, 15.f, 0, 0);
            // z' = 3.25*z - 0.25*z@u3
            gemm(1, M, M, M, zc, M, MM2, 0, u3, M, MM2, 0, 0,
                 zn, M, MM2, 0, BH, 1, -0.25f, nullptr, 0, zc, 3.25f, 0, 0);
            float* tmp = zc; zc = zn; zn = tmp;
        }
        // zc holds pinv(attn2) after 6 iterations

        // av = attn3 @ v    (256 x 64 x 1024)
        gemm(0, M, DH, N,
             attn3, N, (long)H * M * N, (long)M * N,
             qkv + 2 * D, 3 * D, (long)N * 3 * D, 64, 0,
             av, DH, (long)H * M * DH, (long)M * DH,
             BH, H, 1.f, nullptr, 0, nullptr, 0.f, 0, 0);

        // conv residual into ctx (B,N,D layout)
        conv_kernel<<<dim3(N / 128, BH), 256>>>(qkv, ckp, ctx);

        // t = attn1 @ pinv  (1024 x 256 x 256)
        gemm(1, N, M, M,
             attn1, M, (long)N * M, 0,
             zc, M, MM2, 0, 0,
             tt, M, (long)N * M, 0,
             BH, 1, 1.f, nullptr, 0, nullptr, 0.f, 0, 0);

        // ctx += t @ av     (1024 x 64 x 256), strided write into (B,N,D)
        gemm(0, N, DH, M,
             tt, M, (long)H * N * M, (long)N * M,
             av, DH, (long)H * M * DH, (long)M * DH, 0,
             ctx, D, (long)N * D, 64,
             BH, H, 1.f, nullptr, 0, nullptr, 0.f, 1, 0);

        // h += (ctx @ out_w + out_b)[:, -L:]   (remap epilogue)
        gemm(1, B * N, D, D, ctx, D, 0, 0, ow, D, 0, 0, 0,
             h, D, 0, 0, 1, 1, 1.f, ob, 0, nullptr, 0.f, 0, 1);

        // FFN
        ln_kernel<<<B * L, 256>>>(h, x2, ln2_s + (long)i * D, ln2_b + (long)i * D);
        gemm(1, B * L, FF, D, x2, D, 0, 0, w1, FF, 0, 0, 0,
             ff, FF, 0, 0, 1, 1, 1.f, b1, 1, nullptr, 0.f, 0, 0);
        gemm(1, B * L, D, FF, ff, FF, 0, 0, w2, D, 0, 0, 0,
             h, D, 0, 0, 1, 1, 1.f, b2, 0, nullptr, 0.f, 1, 0);
    }

    final_partial_kernel<<<dim3(64, B), 256>>>(h, fin_w, part);
    final_reduce_kernel<<<B, 32>>>(part, fin_b, out);
}

// round 6
// speedup vs baseline: 2.7257x; 1.6630x over previous
#include <cuda_runtime.h>
#include <cuda_fp16.h>
#include <cstdint>
#include <math.h>
#include <mma.h>

using namespace nvcuda;

namespace nys {

constexpr int B = 16, L = 1000, D = 512, H = 8, DH = 64;
constexpr int N = 1024, M = 256, PADN = 24, DEPTH = 6, FF = 2048, KC = 33;
constexpr int BH = B * H;
constexpr float SCALE = 0.125f;   // DH^-0.5

// ------------------------- scratch (static device memory) -------------------
__device__ float g_h   [B * L * D];
__device__ float g_xp  [B * N * D];
__device__ float g_x2  [B * L * D];
__device__ float g_qkv [B * N * 3 * D];
__device__ float g_ql  [BH * M * DH];
__device__ float g_kl  [BH * M * DH];
__device__ float g_attn1[BH * N * M];
__device__ float g_attn3[BH * M * N];
__device__ float g_attn2[BH * M * M];
__device__ float g_z   [BH * M * M];
__device__ float g_z2  [BH * M * M];
__device__ float g_xz  [BH * M * M];
__device__ float g_u1  [BH * M * M];
__device__ float g_u3  [BH * M * M];
__device__ float g_av  [BH * M * DH];
__device__ float g_t   [BH * N * M];
__device__ float g_ctx [B * N * D];
__device__ float g_ff  [B * L * FF];
__device__ float g_scal[2];
__device__ float g_part[B * 64];

// ------------------------- block reduction helpers --------------------------
__device__ __forceinline__ float blkSum(float v, float* sh) {
    int lane = threadIdx.x & 31, w = threadIdx.x >> 5;
#pragma unroll
    for (int o = 16; o; o >>= 1) v += __shfl_xor_sync(0xffffffffu, v, o);
    if (lane == 0) sh[w] = v;
    __syncthreads();
    if (w == 0) {
        float t = (lane < (int)(blockDim.x >> 5)) ? sh[lane] : 0.f;
#pragma unroll
        for (int o = 16; o; o >>= 1) t += __shfl_xor_sync(0xffffffffu, t, o);
        if (lane == 0) sh[32] = t;
    }
    __syncthreads();
    float r = sh[32];
    __syncthreads();
    return r;
}

__device__ __forceinline__ float blkMax(float v, float* sh) {
    int lane = threadIdx.x & 31, w = threadIdx.x >> 5;
#pragma unroll
    for (int o = 16; o; o >>= 1) v = fmaxf(v, __shfl_xor_sync(0xffffffffu, v, o));
    if (lane == 0) sh[w] = v;
    __syncthreads();
    if (w == 0) {
        float t = (lane < (int)(blockDim.x >> 5)) ? sh[lane] : -3.4e38f;
#pragma unroll
        for (int o = 16; o; o >>= 1) t = fmaxf(t, __shfl_xor_sync(0xffffffffu, t, o));
        if (lane == 0) sh[32] = t;
    }
    __syncthreads();
    float r = sh[32];
    __syncthreads();
    return r;
}

// ------------------------- fp16 tensor-core batched GEMM ---------------------
// C = alpha * A(@/@T)B [+ escale*E] [+ bias] [gelu] [accumulate / row-remap]
// A fp32 [m,k] row-major; B fp32 [k,n] (transB=0) or [n,k] (transB=1).
// fp32 -> fp16 RN on staging; fp32 accumulate. Register-prefetch pipeline:
// LDG tile k+1 into regs -> cvt+STS -> sync -> mma tile (LDG for k+2 in flight).
// 256 threads, 8 warps (4x2), warp tile 32 x (NT/2), BM=128, BK=32.
template <int NT>
__global__ void __launch_bounds__(256) hgemm(
    int Kdim,
    const float* __restrict__ A, int lda, long sA1, long sA2,
    const float* __restrict__ Bm, int ldb, long sB1, long sB2, int transB,
    float* __restrict__ C, int ldc, long sC1, long sC2,
    int Hd, float alpha,
    const float* __restrict__ bias, int gelu,
    const float* __restrict__ E, float escale,
    int accumulate, int remap)
{
    constexpr int BM = 128, BK = 32;
    constexpr int LDA = BK + 8;    // 40 halfs
    constexpr int LDB = NT + 8;
    constexpr int MI = 2;          // warp m tiles of 16
    constexpr int NI = NT / 32;    // warp n tiles of 16 (4 or 2)
    constexpr int BREG = NT / 32;  // B float4s per thread per tile

    __shared__ __half sA[BM * LDA];
    __shared__ __half sB[BK * LDB];
    __shared__ float cpad[8][16 * 20];

    int tid = threadIdx.x;
    int wid = tid >> 5, lane = tid & 31;
    int m0 = blockIdx.y * BM, n0 = blockIdx.x * NT;
    int z = blockIdx.z;
    int bb = z / Hd, hh = z - bb * Hd;
    const float* Ap = A + (long)bb * sA1 + (long)hh * sA2;
    const float* Bp = Bm + (long)bb * sB1 + (long)hh * sB2;
    long coff = (long)bb * sC1 + (long)hh * sC2;

    int wm0 = (wid >> 1) * 32;
    int wn0 = (wid & 1) * (NT / 2);

    wmma::fragment<wmma::accumulator, 16, 16, 16, float> acc[MI][NI];
#pragma unroll
    for (int mi = 0; mi < MI; mi++)
#pragma unroll
        for (int ni = 0; ni < NI; ni++) wmma::fill_fragment(acc[mi][ni], 0.f);

    float4 aR[4], bR[BREG];

    auto loadT = [&](int k0) {
#pragma unroll
        for (int t = 0; t < 4; t++) {
            int i = t * 256 + tid;
            int row = i >> 3, kq = i & 7;
            aR[t] = *(const float4*)(Ap + (long)(m0 + row) * lda + k0 + kq * 4);
        }
        if (transB) {
#pragma unroll
            for (int t = 0; t < BREG; t++) {
                int i = t * 256 + tid;
                int n = i >> 3, kq = i & 7;
                bR[t] = *(const float4*)(Bp + (long)(n0 + n) * ldb + k0 + kq * 4);
            }
        } else {
#pragma unroll
            for (int t = 0; t < BREG; t++) {
                int i = t * 256 + tid;
                int row = i / (NT / 4), c4 = i % (NT / 4);
                bR[t] = *(const float4*)(Bp + (long)(k0 + row) * ldb + n0 + c4 * 4);
            }
        }
    };

    auto storeT = [&]() {
#pragma unroll
        for (int t = 0; t < 4; t++) {
            int i = t * 256 + tid;
            int row = i >> 3, kq = i & 7;
            __half2* dst = (__half2*)&sA[row * LDA + kq * 4];
            dst[0] = __floats2half2_rn(aR[t].x, aR[t].y);
            dst[1] = __floats2half2_rn(aR[t].z, aR[t].w);
        }
        if (transB) {
#pragma unroll
            for (int t = 0; t < BREG; t++) {
                int i = t * 256 + tid;
                int n = i >> 3, kq = i & 7;
                sB[(kq * 4 + 0) * LDB + n] = __float2half_rn(bR[t].x);
                sB[(kq * 4 + 1) * LDB + n] = __float2half_rn(bR[t].y);
                sB[(kq * 4 + 2) * LDB + n] = __float2half_rn(bR[t].z);
                sB[(kq * 4 + 3) * LDB + n] = __float2half_rn(bR[t].w);
            }
        } else {
#pragma unroll
            for (int t = 0; t < BREG; t++) {
                int i = t * 256 + tid;
                int row = i / (NT / 4), c4 = i % (NT / 4);
                __half2* dst = (__half2*)&sB[row * LDB + c4 * 4];
                dst[0] = __floats2half2_rn(bR[t].x, bR[t].y);
                dst[1] = __floats2half2_rn(bR[t].z, bR[t].w);
            }
        }
    };

    loadT(0);
    int nk = Kdim / BK;
    for (int c = 0; c < nk; c++) {
        storeT();
        __syncthreads();
        if (c + 1 < nk) loadT((c + 1) * BK);   // LDGs in flight during mma
#pragma unroll
        for (int ks = 0; ks < 2; ks++) {
            wmma::fragment<wmma::matrix_a, 16, 16, 16, __half, wmma::row_major> af[MI];
#pragma unroll
            for (int mi = 0; mi < MI; mi++)
                wmma::load_matrix_sync(af[mi], &sA[(wm0 + mi * 16) * LDA + ks * 16], LDA);
#pragma unroll
            for (int ni = 0; ni < NI; ni++) {
                wmma::fragment<wmma::matrix_b, 16, 16, 16, __half, wmma::row_major> bf;
                wmma::load_matrix_sync(bf, &sB[(ks * 16) * LDB + wn0 + ni * 16], LDB);
#pragma unroll
                for (int mi = 0; mi < MI; mi++)
                    wmma::mma_sync(acc[mi][ni], af[mi], bf, acc[mi][ni]);
            }
        }
        __syncthreads();
    }

    // epilogue: per-warp 16x16 patches staged through smem
#pragma unroll
    for (int mi = 0; mi < MI; mi++) {
#pragma unroll
        for (int ni = 0; ni < NI; ni++) {
            wmma::store_matrix_sync(&cpad[wid][0], acc[mi][ni], 20, wmma::mem_row_major);
            __syncwarp();
#pragma unroll
            for (int j = 0; j < 8; j++) {
                int p = j * 32 + lane;           // 0..255
                int pr = p >> 4, pc = p & 15;
                float v = alpha * cpad[wid][pr * 20 + pc];
                int m = m0 + wm0 + mi * 16 + pr;
                int n = n0 + wn0 + ni * 16 + pc;
                if (E) v += escale * E[coff + (long)m * ldc + n];
                if (bias) v += bias[n];
                if (gelu) v = 0.5f * v * (1.0f + erff(v * 0.70710678118654752f));
                if (remap) {
                    int bI = m >> 10;            // N = 1024
                    int nn = m & 1023;
                    if (nn >= PADN)
                        C[((long)bI * L + (nn - PADN)) * ldc + n] += v;
                } else {
                    long idx = coff + (long)m * ldc + n;
                    if (accumulate) C[idx] += v; else C[idx] = v;
                }
            }
            __syncwarp();
        }
    }
}

// ------------------------- elementwise / reduction kernels -------------------
__global__ void embed_kernel(const int* __restrict__ x, const float* __restrict__ enc,
                             const float* __restrict__ pos, float* __restrict__ h) {
    long idx = (long)blockIdx.x * 256 + threadIdx.x;   // B*L*D total
    int d = (int)(idx % D);
    long bl = idx / D;
    int l = (int)(bl % L);
    h[idx] = enc[(long)x[bl] * D + d] + pos[(long)l * D + d];
}

__global__ void ln_pad_kernel(const float* __restrict__ src, float* __restrict__ dst,
                              const float* __restrict__ s, const float* __restrict__ bia) {
    int row = blockIdx.x;                 // B*N rows
    int b = row >> 10, n = row & 1023;
    int tid = threadIdx.x;                // 256 threads, 2 elems each
    float* out = dst + (long)row * D;
    if (n < PADN) { out[tid] = 0.f; out[tid + 256] = 0.f; return; }
    const float* in = src + ((long)b * L + (n - PADN)) * D;
    __shared__ float sh[33];
    float v0 = in[tid], v1 = in[tid + 256];
    float mu = blkSum(v0 + v1, sh) * (1.0f / D);
    float d0 = v0 - mu, d1 = v1 - mu;
    float var = blkSum(d0 * d0 + d1 * d1, sh) * (1.0f / D);
    float r = rsqrtf(var + 1e-5f);
    out[tid]       = d0 * r * s[tid]       + bia[tid];
    out[tid + 256] = d1 * r * s[tid + 256] + bia[tid + 256];
}

__global__ void ln_kernel(const float* __restrict__ src, float* __restrict__ dst,
                          const float* __restrict__ s, const float* __restrict__ bia) {
    long row = blockIdx.x;                // B*L rows
    int tid = threadIdx.x;
    const float* in = src + row * D;
    float* out = dst + row * D;
    __shared__ float sh[33];
    float v0 = in[tid], v1 = in[tid + 256];
    float mu = blkSum(v0 + v1, sh) * (1.0f / D);
    float d0 = v0 - mu, d1 = v1 - mu;
    float var = blkSum(d0 * d0 + d1 * d1, sh) * (1.0f / D);
    float r = rsqrtf(var + 1e-5f);
    out[tid]       = d0 * r * s[tid]       + bia[tid];
    out[tid + 256] = d1 * r * s[tid + 256] + bia[tid + 256];
}

__global__ void landmark_kernel(const float* __restrict__ qkv,
                                float* __restrict__ ql, float* __restrict__ kl) {
    int idx = blockIdx.x * 256 + threadIdx.x;    // BH*M*DH total
    int d = idx & 63;
    int m = (idx >> 6) & (M - 1);
    int bh = idx >> 14;
    int b = bh >> 3, h = bh & 7;
    const float* base = qkv + ((long)(b * N + m * 4)) * 1536 + h * 64 + d;
    float sq = 0.f, sk = 0.f;
#pragma unroll
    for (int j = 0; j < 4; j++) { sq += base[j * 1536]; sk += base[j * 1536 + 512]; }
    ql[idx] = sq * 0.25f;
    kl[idx] = sk * 0.25f;
}

template <int W>
__global__ void softmax_kernel(float* __restrict__ x) {
    constexpr int PT = W / 256;
    long base = (long)blockIdx.x * W;
    int tid = threadIdx.x;
    __shared__ float sh[33];
    float v[PT];
    float mx = -3.4e38f;
#pragma unroll
    for (int p = 0; p < PT; p++) { v[p] = x[base + tid + p * 256]; mx = fmaxf(mx, v[p]); }
    mx = blkMax(mx, sh);
    float s = 0.f;
#pragma unroll
    for (int p = 0; p < PT; p++) { v[p] = expf(v[p] - mx); s += v[p]; }
    s = blkSum(s, sh);
    float inv = 1.0f / s;
#pragma unroll
    for (int p = 0; p < PT; p++) x[base + tid + p * 256] = v[p] * inv;
}

__global__ void scal_init_kernel(float* scal) {
    if (threadIdx.x < 2) scal[threadIdx.x] = 0.f;
}

__global__ void absrowmax_kernel(const float* __restrict__ x, float* scal) {
    long base = (long)blockIdx.x * M;     // BH*M rows
    __shared__ float sh[33];
    float v = fabsf(x[base + threadIdx.x]);
    float s = blkSum(v, sh);
    if (threadIdx.x == 0)
        atomicMax((unsigned int*)&scal[0], __float_as_uint(s));
}

__global__ void abscolmax_kernel(const float* __restrict__ x, float* scal) {
    const float* p = x + (long)blockIdx.x * M * M;   // BH batches
    int j = threadIdx.x;
    float s = 0.f;
    for (int i = 0; i < M; i++) s += fabsf(p[i * M + j]);
    __shared__ float sh[33];
    float m = blkMax(s, sh);
    if (threadIdx.x == 0)
        atomicMax((unsigned int*)&scal[1], __float_as_uint(m));
}

__global__ void zinit_kernel(const float* __restrict__ x, const float* __restrict__ scal,
                             float* __restrict__ z) {
    long idx = (long)blockIdx.x * 256 + threadIdx.x;  // BH*M*M
    float inv = 1.0f / (scal[0] * scal[1]);
    int j = (int)(idx & 255);
    int i = (int)((idx >> 8) & 255);
    long bh = idx >> 16;
    z[idx] = x[(bh << 16) + (long)j * M + i] * inv;
}

__global__ void conv_kernel(const float* __restrict__ qkv, const float* __restrict__ ck,
                            float* __restrict__ ctx) {
    __shared__ float sv[160 * 64];
    __shared__ float sck[KC];
    int bh = blockIdx.y;
    int b = bh >> 3, h = bh & 7;
    int n0 = blockIdx.x * 128;
    int tid = threadIdx.x;
    if (tid < KC) sck[tid] = ck[h * KC + tid];
    for (int i = tid; i < 160 * 64; i += 256) {
        int r = i >> 6, d = i & 63;
        int n = n0 - 16 + r;
        float v = 0.f;
        if (n >= 0 && n < N) v = qkv[((long)(b * N + n)) * 1536 + 1024 + h * 64 + d];
        sv[i] = v;
    }
    __syncthreads();
    for (int o = tid; o < 128 * 64; o += 256) {
        int nl = o >> 6, d = o & 63;
        float s = 0.f;
#pragma unroll
        for (int t = 0; t < KC; t++) s += sck[t] * sv[(nl + t) * 64 + d];
        ctx[((long)(b * N + n0 + nl)) * D + h * 64 + d] = s;
    }
}

__global__ void final_partial_kernel(const float* __restrict__ h, const float* __restrict__ fw,
                                     float* __restrict__ part) {
    int b = blockIdx.y, c = blockIdx.x;   // 64 chunks per batch
    const int CHK = (L * D) / 64;         // 8000
    long base = (long)b * L * D;
    float s = 0.f;
    for (int i = c * CHK + threadIdx.x; i < (c + 1) * CHK; i += 256)
        s += h[base + i] * fw[i];
    __shared__ float sh[33];
    s = blkSum(s, sh);
    if (threadIdx.x == 0) part[b * 64 + c] = s;
}

__global__ void final_reduce_kernel(const float* __restrict__ part, const float* __restrict__ fb,
                                    float* __restrict__ out) {
    int b = blockIdx.x;
    int t = threadIdx.x;  // 32
    float v = part[b * 64 + t] + part[b * 64 + t + 32];
#pragma unroll
    for (int o = 16; o; o >>= 1) v += __shfl_xor_sync(0xffffffffu, v, o);
    if (t == 0) out[b] = v + fb[0];
}

} // namespace nys

// ------------------------- host orchestration --------------------------------
static float* nys_sym(const void* s) {
    void* p = nullptr;
    cudaGetSymbolAddress(&p, s);
    return (float*)p;
}

static void gemm(int cfg128, int Mdim, int Ndim, int K,
                 const float* A, int lda, long sA1, long sA2,
                 const float* Bm, int ldb, long sB1, long sB2, int tB,
                 float* C, int ldc, long sC1, long sC2,
                 int batch, int Hd, float alpha,
                 const float* bias, int gelu, const float* E, float es,
                 int acc, int remap) {
    if (cfg128) {
        dim3 g(Ndim / 128, Mdim / 128, batch);
        nys::hgemm<128><<<g, 256>>>(
            K, A, lda, sA1, sA2, Bm, ldb, sB1, sB2, tB,
            C, ldc, sC1, sC2, Hd, alpha, bias, gelu, E, es, acc, remap);
    } else {
        dim3 g(Ndim / 64, Mdim / 128, batch);
        nys::hgemm<64><<<g, 256>>>(
            K, A, lda, sA1, sA2, Bm, ldb, sB1, sB2, tB,
            C, ldc, sC1, sC2, Hd, alpha, bias, gelu, E, es, acc, remap);
    }
}

extern "C" void kernel_launch(void* const* d_in, const int* in_sizes, int n_in,
                              void* d_out, int out_size) {
    using namespace nys;
    (void)in_sizes; (void)n_in; (void)out_size;

    const int*   xin    = (const int*)  d_in[0];
    const float* enc    = (const float*)d_in[1];
    const float* pos    = (const float*)d_in[2];
    const float* ln1_s  = (const float*)d_in[3];
    const float* ln1_b  = (const float*)d_in[4];
    const float* qkv_w  = (const float*)d_in[5];
    const float* out_w  = (const float*)d_in[6];
    const float* out_b  = (const float*)d_in[7];
    const float* conv_k = (const float*)d_in[8];
    const float* ln2_s  = (const float*)d_in[9];
    const float* ln2_b  = (const float*)d_in[10];
    const float* ff_w1  = (const float*)d_in[11];
    const float* ff_b1  = (const float*)d_in[12];
    const float* ff_w2  = (const float*)d_in[13];
    const float* ff_b2  = (const float*)d_in[14];
    const float* fin_w  = (const float*)d_in[15];
    const float* fin_b  = (const float*)d_in[16];
    float* out = (float*)d_out;

    float* h     = nys_sym(g_h);
    float* xp    = nys_sym(g_xp);
    float* x2    = nys_sym(g_x2);
    float* qkv   = nys_sym(g_qkv);
    float* ql    = nys_sym(g_ql);
    float* kl    = nys_sym(g_kl);
    float* attn1 = nys_sym(g_attn1);
    float* attn3 = nys_sym(g_attn3);
    float* attn2 = nys_sym(g_attn2);
    float* zb    = nys_sym(g_z);
    float* zb2   = nys_sym(g_z2);
    float* xz    = nys_sym(g_xz);
    float* u1    = nys_sym(g_u1);
    float* u3    = nys_sym(g_u3);
    float* av    = nys_sym(g_av);
    float* tt    = nys_sym(g_t);
    float* ctx   = nys_sym(g_ctx);
    float* ff    = nys_sym(g_ff);
    float* scal  = nys_sym(g_scal);
    float* part  = nys_sym(g_part);

    const long MM2 = (long)M * M;

    embed_kernel<<<(B * L * D) / 256, 256>>>(xin, enc, pos, h);

    for (int i = 0; i < DEPTH; i++) {
        const float* qw  = qkv_w  + (long)i * D * 3 * D;
        const float* ow  = out_w  + (long)i * D * D;
        const float* ob  = out_b  + (long)i * D;
        const float* ckp = conv_k + (long)i * H * KC;
        const float* w1  = ff_w1  + (long)i * D * FF;
        const float* b1  = ff_b1  + (long)i * FF;
        const float* w2  = ff_w2  + (long)i * FF * D;
        const float* b2  = ff_b2  + (long)i * D;

        // LN1 + left-pad into xp (B*N rows)
        ln_pad_kernel<<<B * N, 256>>>(h, xp, ln1_s + (long)i * D, ln1_b + (long)i * D);

        // qkv = xp @ qkv_w   (16384 x 1536 x 512)
        gemm(1, B * N, 3 * D, D, xp, D, 0, 0, qw, 3 * D, 0, 0, 0,
             qkv, 3 * D, 0, 0, 1, 1, 1.f, nullptr, 0, nullptr, 0.f, 0, 0);

        // landmark means (q_l unscaled; SCALE folded into logit alphas)
        landmark_kernel<<<(BH * M * DH) / 256, 256>>>(qkv, ql, kl);

        // attn1 = softmax(SCALE * q @ k_l^T)   (1024 x 256 x 64, batched bh)
        gemm(1, N, M, DH,
             qkv, 3 * D, (long)N * 3 * D, 64,
             kl, DH, (long)H * M * DH, (long)M * DH, 1,
             attn1, M, (long)H * N * M, (long)N * M,
             BH, H, SCALE, nullptr, 0, nullptr, 0.f, 0, 0);
        softmax_kernel<256><<<BH * N, 256>>>(attn1);

        // attn2 = softmax(SCALE * q_l @ k_l^T) (256 x 256 x 64)
        gemm(1, M, M, DH,
             ql, DH, (long)H * M * DH, (long)M * DH,
             kl, DH, (long)H * M * DH, (long)M * DH, 1,
             attn2, M, (long)H * M * M, MM2,
             BH, H, SCALE, nullptr, 0, nullptr, 0.f, 0, 0);
        softmax_kernel<256><<<BH * M, 256>>>(attn2);

        // attn3 = softmax(SCALE * q_l @ k^T)   (256 x 1024 x 64)
        gemm(1, M, N, DH,
             ql, DH, (long)H * M * DH, (long)M * DH,
             qkv + D, 3 * D, (long)N * 3 * D, 64, 1,
             attn3, N, (long)H * M * N, (long)M * N,
             BH, H, SCALE, nullptr, 0, nullptr, 0.f, 0, 0);
        softmax_kernel<1024><<<BH * M, 256>>>(attn3);

        // Moore-Penrose pinv of attn2 (6 iterations)
        scal_init_kernel<<<1, 32>>>(scal);
        absrowmax_kernel<<<BH * M, 256>>>(attn2, scal);
        abscolmax_kernel<<<BH, 256>>>(attn2, scal);
        zinit_kernel<<<(BH * M * M) / 256, 256>>>(attn2, scal, zb);

        float* zc = zb;
        float* zn = zb2;
        for (int it = 0; it < 6; it++) {
            // xz = x @ z
            gemm(1, M, M, M, attn2, M, MM2, 0, zc, M, MM2, 0, 0,
                 xz, M, MM2, 0, BH, 1, 1.f, nullptr, 0, nullptr, 0.f, 0, 0);
            // u1 = 7*xz - xz@xz
            gemm(1, M, M, M, xz, M, MM2, 0, xz, M, MM2, 0, 0,
                 u1, M, MM2, 0, BH, 1, -1.f, nullptr, 0, xz, 7.f, 0, 0);
            // u3 = 15*xz - xz@u1
            gemm(1, M, M, M, xz, M, MM2, 0, u1, M, MM2, 0, 0,
                 u3, M, MM2, 0, BH, 1, -1.f, nullptr, 0, xz, 15.f, 0, 0);
            // z' = 3.25*z - 0.25*z@u3
            gemm(1, M, M, M, zc, M, MM2, 0, u3, M, MM2, 0, 0,
                 zn, M, MM2, 0, BH, 1, -0.25f, nullptr, 0, zc, 3.25f, 0, 0);
            float* tmp = zc; zc = zn; zn = tmp;
        }
        // zc holds pinv(attn2) after 6 iterations

        // av = attn3 @ v    (256 x 64 x 1024)
        gemm(0, M, DH, N,
             attn3, N, (long)H * M * N, (long)M * N,
             qkv + 2 * D, 3 * D, (long)N * 3 * D, 64, 0,
             av, DH, (long)H * M * DH, (long)M * DH,
             BH, H, 1.f, nullptr, 0, nullptr, 0.f, 0, 0);

        // conv residual into ctx (B,N,D layout)
        conv_kernel<<<dim3(N / 128, BH), 256>>>(qkv, ckp, ctx);

        // t = attn1 @ pinv  (1024 x 256 x 256)
        gemm(1, N, M, M,
             attn1, M, (long)N * M, 0,
             zc, M, MM2, 0, 0,
             tt, M, (long)N * M, 0,
             BH, 1, 1.f, nullptr, 0, nullptr, 0.f, 0, 0);

        // ctx += t @ av     (1024 x 64 x 256), strided write into (B,N,D)
        gemm(0, N, DH, M,
             tt, M, (long)H * N * M, (long)N * M,
             av, DH, (long)H * M * DH, (long)M * DH, 0,
             ctx, D, (long)N * D, 64,
             BH, H, 1.f, nullptr, 0, nullptr, 0.f, 1, 0);

        // h += (ctx @ out_w + out_b)[:, -L:]   (remap epilogue)
        gemm(1, B * N, D, D, ctx, D, 0, 0, ow, D, 0, 0, 0,
             h, D, 0, 0, 1, 1, 1.f, ob, 0, nullptr, 0.f, 0, 1);

        // FFN
        ln_kernel<<<B * L, 256>>>(h, x2, ln2_s + (long)i * D, ln2_b + (long)i * D);
        gemm(1, B * L, FF, D, x2, D, 0, 0, w1, FF, 0, 0, 0,
             ff, FF, 0, 0, 1, 1, 1.f, b1, 1, nullptr, 0.f, 0, 0);
        gemm(1, B * L, D, FF, ff, FF, 0, 0, w2, D, 0, 0, 0,
             h, D, 0, 0, 1, 1, 1.f, b2, 0, nullptr, 0.f, 1, 0);
    }

    final_partial_kernel<<<dim3(64, B), 256>>>(h, fin_w, part);
    final_reduce_kernel<<<B, 32>>>(part, fin_b, out);
}

// round 8
// speedup vs baseline: 3.3996x; 1.2472x over previous
#include <cuda_runtime.h>
#include <cuda_fp16.h>
#include <cstdint>
#include <math.h>
#include <mma.h>

using namespace nvcuda;

namespace nys {

constexpr int B = 16, L = 1000, D = 512, H = 8, DH = 64;
constexpr int N = 1024, M = 256, PADN = 24, DEPTH = 6, FF = 2048, KC = 33;
constexpr int BH = B * H;
constexpr float SCALE = 0.125f;   // DH^-0.5

// ------------------------- scratch (static device memory) -------------------
__device__ float g_h   [B * L * D];
__device__ float g_xp  [B * N * D];
__device__ float g_x2  [B * L * D];
__device__ float g_qkv [B * N * 3 * D];
__device__ float g_ql  [BH * M * DH];
__device__ float g_kl  [BH * M * DH];
__device__ float g_attn1[BH * N * M];
__device__ float g_attn3[BH * M * N];
__device__ float g_attn2[BH * M * M];
__device__ float g_z   [BH * M * M];
__device__ float g_z2  [BH * M * M];
__device__ float g_xz  [BH * M * M];
__device__ float g_u1  [BH * M * M];
__device__ float g_u3  [BH * M * M];
__device__ float g_av  [BH * M * DH];
__device__ float g_t   [BH * N * M];
__device__ float g_ctx [B * N * D];
__device__ float g_ff  [B * L * FF];
__device__ float g_scal[2];
__device__ float g_part[B * 64];

// ------------------------- block reduction helpers --------------------------
__device__ __forceinline__ float blkSum(float v, float* sh) {
    int lane = threadIdx.x & 31, w = threadIdx.x >> 5;
#pragma unroll
    for (int o = 16; o; o >>= 1) v += __shfl_xor_sync(0xffffffffu, v, o);
    if (lane == 0) sh[w] = v;
    __syncthreads();
    if (w == 0) {
        float t = (lane < (int)(blockDim.x >> 5)) ? sh[lane] : 0.f;
#pragma unroll
        for (int o = 16; o; o >>= 1) t += __shfl_xor_sync(0xffffffffu, t, o);
        if (lane == 0) sh[32] = t;
    }
    __syncthreads();
    float r = sh[32];
    __syncthreads();
    return r;
}

__device__ __forceinline__ float blkMax(float v, float* sh) {
    int lane = threadIdx.x & 31, w = threadIdx.x >> 5;
#pragma unroll
    for (int o = 16; o; o >>= 1) v = fmaxf(v, __shfl_xor_sync(0xffffffffu, v, o));
    if (lane == 0) sh[w] = v;
    __syncthreads();
    if (w == 0) {
        float t = (lane < (int)(blockDim.x >> 5)) ? sh[lane] : -3.4e38f;
#pragma unroll
        for (int o = 16; o; o >>= 1) t = fmaxf(t, __shfl_xor_sync(0xffffffffu, t, o));
        if (lane == 0) sh[32] = t;
    }
    __syncthreads();
    float r = sh[32];
    __syncthreads();
    return r;
}

// ------------------------- fp16 tensor-core batched GEMM ---------------------
// C = alpha * A(@/@T)B [+ escale*E] [+ bias] [gelu] [accumulate / row-remap]
// A fp32 [m,k] row-major; B fp32 [k,n] (transB=0) or [n,k] (transB=1).
// fp32 -> fp16 RN on staging; fp32 accumulate.
// Pipeline: register prefetch (LDG tile c+1 during MMA of tile c) +
// double-buffered smem (STS of c+1 overlaps nothing-blocking, ONE sync/iter).
// Fast fragment epilogue when no bias/gelu/remap (covers pinv/qkv/logits/t/av/ctx).
// 256 threads, 8 warps (4x2), warp tile 32 x (NT/2), BM=128, BK=32.
template <int NT>
__global__ void __launch_bounds__(256) hgemm(
    int Kdim,
    const float* __restrict__ A, int lda, long sA1, long sA2,
    const float* __restrict__ Bm, int ldb, long sB1, long sB2, int transB,
    float* __restrict__ C, int ldc, long sC1, long sC2,
    int Hd, float alpha,
    const float* __restrict__ bias, int gelu,
    const float* __restrict__ E, float escale,
    int accumulate, int remap)
{
    constexpr int BM = 128, BK = 32;
    constexpr int LDA = BK + 8;    // 40 halfs
    constexpr int LDB = NT + 8;
    constexpr int MI = 2;          // warp m tiles of 16
    constexpr int NI = NT / 32;    // warp n tiles of 16 (4 or 2)
    constexpr int BREG = NT / 32;  // B float4s per thread per tile

    __shared__ __half sA[2][BM * LDA];
    __shared__ __half sB[2][BK * LDB];
    __shared__ float cpad[8][16 * 20];

    int tid = threadIdx.x;
    int wid = tid >> 5, lane = tid & 31;
    int m0 = blockIdx.y * BM, n0 = blockIdx.x * NT;
    int z = blockIdx.z;
    int bb = z / Hd, hh = z - bb * Hd;
    const float* Ap = A + (long)bb * sA1 + (long)hh * sA2;
    const float* Bp = Bm + (long)bb * sB1 + (long)hh * sB2;
    long coff = (long)bb * sC1 + (long)hh * sC2;

    int wm0 = (wid >> 1) * 32;
    int wn0 = (wid & 1) * (NT / 2);

    wmma::fragment<wmma::accumulator, 16, 16, 16, float> acc[MI][NI];
#pragma unroll
    for (int mi = 0; mi < MI; mi++)
#pragma unroll
        for (int ni = 0; ni < NI; ni++) wmma::fill_fragment(acc[mi][ni], 0.f);

    float4 aR[4], bR[BREG];

    auto loadT = [&](int k0) {
#pragma unroll
        for (int t = 0; t < 4; t++) {
            int i = t * 256 + tid;
            int row = i >> 3, kq = i & 7;
            aR[t] = *(const float4*)(Ap + (long)(m0 + row) * lda + k0 + kq * 4);
        }
        if (transB) {
#pragma unroll
            for (int t = 0; t < BREG; t++) {
                int i = t * 256 + tid;
                int n = i >> 3, kq = i & 7;
                bR[t] = *(const float4*)(Bp + (long)(n0 + n) * ldb + k0 + kq * 4);
            }
        } else {
#pragma unroll
            for (int t = 0; t < BREG; t++) {
                int i = t * 256 + tid;
                int row = i / (NT / 4), c4 = i % (NT / 4);
                bR[t] = *(const float4*)(Bp + (long)(k0 + row) * ldb + n0 + c4 * 4);
            }
        }
    };

    auto storeT = [&](int bf) {
#pragma unroll
        for (int t = 0; t < 4; t++) {
            int i = t * 256 + tid;
            int row = i >> 3, kq = i & 7;
            __half2* dst = (__half2*)&sA[bf][row * LDA + kq * 4];
            dst[0] = __floats2half2_rn(aR[t].x, aR[t].y);
            dst[1] = __floats2half2_rn(aR[t].z, aR[t].w);
        }
        if (transB) {
#pragma unroll
            for (int t = 0; t < BREG; t++) {
                int i = t * 256 + tid;
                int n = i >> 3, kq = i & 7;
                sB[bf][(kq * 4 + 0) * LDB + n] = __float2half_rn(bR[t].x);
                sB[bf][(kq * 4 + 1) * LDB + n] = __float2half_rn(bR[t].y);
                sB[bf][(kq * 4 + 2) * LDB + n] = __float2half_rn(bR[t].z);
                sB[bf][(kq * 4 + 3) * LDB + n] = __float2half_rn(bR[t].w);
            }
        } else {
#pragma unroll
            for (int t = 0; t < BREG; t++) {
                int i = t * 256 + tid;
                int row = i / (NT / 4), c4 = i % (NT / 4);
                __half2* dst = (__half2*)&sB[bf][row * LDB + c4 * 4];
                dst[0] = __floats2half2_rn(bR[t].x, bR[t].y);
                dst[1] = __floats2half2_rn(bR[t].z, bR[t].w);
            }
        }
    };

    loadT(0);
    storeT(0);
    __syncthreads();
    int nk = Kdim / BK;
    for (int c = 0; c < nk; c++) {
        if (c + 1 < nk) loadT((c + 1) * BK);   // LDGs in flight during mma
        int bf = c & 1;
#pragma unroll
        for (int ks = 0; ks < 2; ks++) {
            wmma::fragment<wmma::matrix_a, 16, 16, 16, __half, wmma::row_major> af[MI];
#pragma unroll
            for (int mi = 0; mi < MI; mi++)
                wmma::load_matrix_sync(af[mi], &sA[bf][(wm0 + mi * 16) * LDA + ks * 16], LDA);
#pragma unroll
            for (int ni = 0; ni < NI; ni++) {
                wmma::fragment<wmma::matrix_b, 16, 16, 16, __half, wmma::row_major> bfr;
                wmma::load_matrix_sync(bfr, &sB[bf][(ks * 16) * LDB + wn0 + ni * 16], LDB);
#pragma unroll
                for (int mi = 0; mi < MI; mi++)
                    wmma::mma_sync(acc[mi][ni], af[mi], bfr, acc[mi][ni]);
            }
        }
        if (c + 1 < nk) storeT((c + 1) & 1);   // different buffer; safe pre-sync
        __syncthreads();
    }

    if (!bias && !gelu && !remap) {
        // fast fragment epilogue: alpha, escale*E, accumulate, direct store
#pragma unroll
        for (int mi = 0; mi < MI; mi++) {
#pragma unroll
            for (int ni = 0; ni < NI; ni++) {
                long base = coff + (long)(m0 + wm0 + mi * 16) * ldc + (n0 + wn0 + ni * 16);
#pragma unroll
                for (int e = 0; e < acc[mi][ni].num_elements; e++)
                    acc[mi][ni].x[e] *= alpha;
                if (E) {
                    wmma::fragment<wmma::accumulator, 16, 16, 16, float> ef;
                    wmma::load_matrix_sync(ef, E + base, ldc, wmma::mem_row_major);
#pragma unroll
                    for (int e = 0; e < ef.num_elements; e++)
                        acc[mi][ni].x[e] += escale * ef.x[e];
                }
                if (accumulate) {
                    wmma::fragment<wmma::accumulator, 16, 16, 16, float> cf;
                    wmma::load_matrix_sync(cf, C + base, ldc, wmma::mem_row_major);
#pragma unroll
                    for (int e = 0; e < cf.num_elements; e++)
                        acc[mi][ni].x[e] += cf.x[e];
                }
                wmma::store_matrix_sync(C + base, acc[mi][ni], ldc, wmma::mem_row_major);
            }
        }
        return;
    }

    // slow epilogue: per-warp 16x16 patches staged through smem
#pragma unroll
    for (int mi = 0; mi < MI; mi++) {
#pragma unroll
        for (int ni = 0; ni < NI; ni++) {
            wmma::store_matrix_sync(&cpad[wid][0], acc[mi][ni], 20, wmma::mem_row_major);
            __syncwarp();
#pragma unroll
            for (int j = 0; j < 8; j++) {
                int p = j * 32 + lane;           // 0..255
                int pr = p >> 4, pc = p & 15;
                float v = alpha * cpad[wid][pr * 20 + pc];
                int m = m0 + wm0 + mi * 16 + pr;
                int n = n0 + wn0 + ni * 16 + pc;
                if (E) v += escale * E[coff + (long)m * ldc + n];
                if (bias) v += bias[n];
                if (gelu) v = 0.5f * v * (1.0f + erff(v * 0.70710678118654752f));
                if (remap) {
                    int bI = m >> 10;            // N = 1024
                    int nn = m & 1023;
                    if (nn >= PADN)
                        C[((long)bI * L + (nn - PADN)) * ldc + n] += v;
                } else {
                    long idx = coff + (long)m * ldc + n;
                    if (accumulate) C[idx] += v; else C[idx] = v;
                }
            }
            __syncwarp();
        }
    }
}

// ------------------------- elementwise / reduction kernels -------------------
__global__ void embed_kernel(const int* __restrict__ x, const float* __restrict__ enc,
                             const float* __restrict__ pos, float* __restrict__ h) {
    long idx = (long)blockIdx.x * 256 + threadIdx.x;   // B*L*D total
    int d = (int)(idx % D);
    long bl = idx / D;
    int l = (int)(bl % L);
    h[idx] = enc[(long)x[bl] * D + d] + pos[(long)l * D + d];
}

__global__ void ln_pad_kernel(const float* __restrict__ src, float* __restrict__ dst,
                              const float* __restrict__ s, const float* __restrict__ bia) {
    int row = blockIdx.x;                 // B*N rows
    int b = row >> 10, n = row & 1023;
    int tid = threadIdx.x;                // 256 threads, 2 elems each
    float* out = dst + (long)row * D;
    if (n < PADN) { out[tid] = 0.f; out[tid + 256] = 0.f; return; }
    const float* in = src + ((long)b * L + (n - PADN)) * D;
    __shared__ float sh[33];
    float v0 = in[tid], v1 = in[tid + 256];
    float mu = blkSum(v0 + v1, sh) * (1.0f / D);
    float d0 = v0 - mu, d1 = v1 - mu;
    float var = blkSum(d0 * d0 + d1 * d1, sh) * (1.0f / D);
    float r = rsqrtf(var + 1e-5f);
    out[tid]       = d0 * r * s[tid]       + bia[tid];
    out[tid + 256] = d1 * r * s[tid + 256] + bia[tid + 256];
}

__global__ void ln_kernel(const float* __restrict__ src, float* __restrict__ dst,
                          const float* __restrict__ s, const float* __restrict__ bia) {
    long row = blockIdx.x;                // B*L rows
    int tid = threadIdx.x;
    const float* in = src + row * D;
    float* out = dst + row * D;
    __shared__ float sh[33];
    float v0 = in[tid], v1 = in[tid + 256];
    float mu = blkSum(v0 + v1, sh) * (1.0f / D);
    float d0 = v0 - mu, d1 = v1 - mu;
    float var = blkSum(d0 * d0 + d1 * d1, sh) * (1.0f / D);
    float r = rsqrtf(var + 1e-5f);
    out[tid]       = d0 * r * s[tid]       + bia[tid];
    out[tid + 256] = d1 * r * s[tid + 256] + bia[tid + 256];
}

__global__ void landmark_kernel(const float* __restrict__ qkv,
                                float* __restrict__ ql, float* __restrict__ kl) {
    int idx = blockIdx.x * 256 + threadIdx.x;    // BH*M*DH total
    int d = idx & 63;
    int m = (idx >> 6) & (M - 1);
    int bh = idx >> 14;
    int b = bh >> 3, h = bh & 7;
    const float* base = qkv + ((long)(b * N + m * 4)) * 1536 + h * 64 + d;
    float sq = 0.f, sk = 0.f;
#pragma unroll
    for (int j = 0; j < 4; j++) { sq += base[j * 1536]; sk += base[j * 1536 + 512]; }
    ql[idx] = sq * 0.25f;
    kl[idx] = sk * 0.25f;
}

template <int W>
__global__ void softmax_kernel(float* __restrict__ x) {
    constexpr int PT = W / 256;
    long base = (long)blockIdx.x * W;
    int tid = threadIdx.x;
    __shared__ float sh[33];
    float v[PT];
    float mx = -3.4e38f;
#pragma unroll
    for (int p = 0; p < PT; p++) { v[p] = x[base + tid + p * 256]; mx = fmaxf(mx, v[p]); }
    mx = blkMax(mx, sh);
    float s = 0.f;
#pragma unroll
    for (int p = 0; p < PT; p++) { v[p] = expf(v[p] - mx); s += v[p]; }
    s = blkSum(s, sh);
    float inv = 1.0f / s;
#pragma unroll
    for (int p = 0; p < PT; p++) x[base + tid + p * 256] = v[p] * inv;
}

__global__ void scal_init_kernel(float* scal) {
    if (threadIdx.x < 2) scal[threadIdx.x] = 0.f;
}

__global__ void absrowmax_kernel(const float* __restrict__ x, float* scal) {
    long base = (long)blockIdx.x * M;     // BH*M rows
    __shared__ float sh[33];
    float v = fabsf(x[base + threadIdx.x]);
    float s = blkSum(v, sh);
    if (threadIdx.x == 0)
        atomicMax((unsigned int*)&scal[0], __float_as_uint(s));
}

__global__ void abscolmax_kernel(const float* __restrict__ x, float* scal) {
    const float* p = x + (long)blockIdx.x * M * M;   // BH batches
    int j = threadIdx.x;
    float s = 0.f;
    for (int i = 0; i < M; i++) s += fabsf(p[i * M + j]);
    __shared__ float sh[33];
    float m = blkMax(s, sh);
    if (threadIdx.x == 0)
        atomicMax((unsigned int*)&scal[1], __float_as_uint(m));
}

__global__ void zinit_kernel(const float* __restrict__ x, const float* __restrict__ scal,
                             float* __restrict__ z) {
    long idx = (long)blockIdx.x * 256 + threadIdx.x;  // BH*M*M
    float inv = 1.0f / (scal[0] * scal[1]);
    int j = (int)(idx & 255);
    int i = (int)((idx >> 8) & 255);
    long bh = idx >> 16;
    z[idx] = x[(bh << 16) + (long)j * M + i] * inv;
}

__global__ void conv_kernel(const float* __restrict__ qkv, const float* __restrict__ ck,
                            float* __restrict__ ctx) {
    __shared__ float sv[160 * 64];
    __shared__ float sck[KC];
    int bh = blockIdx.y;
    int b = bh >> 3, h = bh & 7;
    int n0 = blockIdx.x * 128;
    int tid = threadIdx.x;
    if (tid < KC) sck[tid] = ck[h * KC + tid];
    for (int i = tid; i < 160 * 64; i += 256) {
        int r = i >> 6, d = i & 63;
        int n = n0 - 16 + r;
        float v = 0.f;
        if (n >= 0 && n < N) v = qkv[((long)(b * N + n)) * 1536 + 1024 + h * 64 + d];
        sv[i] = v;
    }
    __syncthreads();
    for (int o = tid; o < 128 * 64; o += 256) {
        int nl = o >> 6, d = o & 63;
        float s = 0.f;
#pragma unroll
        for (int t = 0; t < KC; t++) s += sck[t] * sv[(nl + t) * 64 + d];
        ctx[((long)(b * N + n0 + nl)) * D + h * 64 + d] = s;
    }
}

__global__ void final_partial_kernel(const float* __restrict__ h, const float* __restrict__ fw,
                                     float* __restrict__ part) {
    int b = blockIdx.y, c = blockIdx.x;   // 64 chunks per batch
    const int CHK = (L * D) / 64;         // 8000
    long base = (long)b * L * D;
    float s = 0.f;
    for (int i = c * CHK + threadIdx.x; i < (c + 1) * CHK; i += 256)
        s += h[base + i] * fw[i];
    __shared__ float sh[33];
    s = blkSum(s, sh);
    if (threadIdx.x == 0) part[b * 64 + c] = s;
}

__global__ void final_reduce_kernel(const float* __restrict__ part, const float* __restrict__ fb,
                                    float* __restrict__ out) {
    int b = blockIdx.x;
    int t = threadIdx.x;  // 32
    float v = part[b * 64 + t] + part[b * 64 + t + 32];
#pragma unroll
    for (int o = 16; o; o >>= 1) v += __shfl_xor_sync(0xffffffffu, v, o);
    if (t == 0) out[b] = v + fb[0];
}

} // namespace nys

// ------------------------- host orchestration --------------------------------
static float* nys_sym(const void* s) {
    void* p = nullptr;
    cudaGetSymbolAddress(&p, s);
    return (float*)p;
}

static void gemm(int cfg128, int Mdim, int Ndim, int K,
                 const float* A, int lda, long sA1, long sA2,
                 const float* Bm, int ldb, long sB1, long sB2, int tB,
                 float* C, int ldc, long sC1, long sC2,
                 int batch, int Hd, float alpha,
                 const float* bias, int gelu, const float* E, float es,
                 int acc, int remap) {
    if (cfg128) {
        dim3 g(Ndim / 128, Mdim / 128, batch);
        nys::hgemm<128><<<g, 256>>>(
            K, A, lda, sA1, sA2, Bm, ldb, sB1, sB2, tB,
            C, ldc, sC1, sC2, Hd, alpha, bias, gelu, E, es, acc, remap);
    } else {
        dim3 g(Ndim / 64, Mdim / 128, batch);
        nys::hgemm<64><<<g, 256>>>(
            K, A, lda, sA1, sA2, Bm, ldb, sB1, sB2, tB,
            C, ldc, sC1, sC2, Hd, alpha, bias, gelu, E, es, acc, remap);
    }
}

extern "C" void kernel_launch(void* const* d_in, const int* in_sizes, int n_in,
                              void* d_out, int out_size) {
    using namespace nys;
    (void)in_sizes; (void)n_in; (void)out_size;

    const int*   xin    = (const int*)  d_in[0];
    const float* enc    = (const float*)d_in[1];
    const float* pos    = (const float*)d_in[2];
    const float* ln1_s  = (const float*)d_in[3];
    const float* ln1_b  = (const float*)d_in[4];
    const float* qkv_w  = (const float*)d_in[5];
    const float* out_w  = (const float*)d_in[6];
    const float* out_b  = (const float*)d_in[7];
    const float* conv_k = (const float*)d_in[8];
    const float* ln2_s  = (const float*)d_in[9];
    const float* ln2_b  = (const float*)d_in[10];
    const float* ff_w1  = (const float*)d_in[11];
    const float* ff_b1  = (const float*)d_in[12];
    const float* ff_w2  = (const float*)d_in[13];
    const float* ff_b2  = (const float*)d_in[14];
    const float* fin_w  = (const float*)d_in[15];
    const float* fin_b  = (const float*)d_in[16];
    float* out = (float*)d_out;

    float* h     = nys_sym(g_h);
    float* xp    = nys_sym(g_xp);
    float* x2    = nys_sym(g_x2);
    float* qkv   = nys_sym(g_qkv);
    float* ql    = nys_sym(g_ql);
    float* kl    = nys_sym(g_kl);
    float* attn1 = nys_sym(g_attn1);
    float* attn3 = nys_sym(g_attn3);
    float* attn2 = nys_sym(g_attn2);
    float* zb    = nys_sym(g_z);
    float* zb2   = nys_sym(g_z2);
    float* xz    = nys_sym(g_xz);
    float* u1    = nys_sym(g_u1);
    float* u3    = nys_sym(g_u3);
    float* av    = nys_sym(g_av);
    float* tt    = nys_sym(g_t);
    float* ctx   = nys_sym(g_ctx);
    float* ff    = nys_sym(g_ff);
    float* scal  = nys_sym(g_scal);
    float* part  = nys_sym(g_part);

    const long MM2 = (long)M * M;

    embed_kernel<<<(B * L * D) / 256, 256>>>(xin, enc, pos, h);

    for (int i = 0; i < DEPTH; i++) {
        const float* qw  = qkv_w  + (long)i * D * 3 * D;
        const float* ow  = out_w  + (long)i * D * D;
        const float* ob  = out_b  + (long)i * D;
        const float* ckp = conv_k + (long)i * H * KC;
        const float* w1  = ff_w1  + (long)i * D * FF;
        const float* b1  = ff_b1  + (long)i * FF;
        const float* w2  = ff_w2  + (long)i * FF * D;
        const float* b2  = ff_b2  + (long)i * D;

        // LN1 + left-pad into xp (B*N rows)
        ln_pad_kernel<<<B * N, 256>>>(h, xp, ln1_s + (long)i * D, ln1_b + (long)i * D);

        // qkv = xp @ qkv_w   (16384 x 1536 x 512)
        gemm(1, B * N, 3 * D, D, xp, D, 0, 0, qw, 3 * D, 0, 0, 0,
             qkv, 3 * D, 0, 0, 1, 1, 1.f, nullptr, 0, nullptr, 0.f, 0, 0);

        // landmark means (q_l unscaled; SCALE folded into logit alphas)
        landmark_kernel<<<(BH * M * DH) / 256, 256>>>(qkv, ql, kl);

        // attn1 = softmax(SCALE * q @ k_l^T)   (1024 x 256 x 64, batched bh)
        gemm(1, N, M, DH,
             qkv, 3 * D, (long)N * 3 * D, 64,
             kl, DH, (long)H * M * DH, (long)M * DH, 1,
             attn1, M, (long)H * N * M, (long)N * M,
             BH, H, SCALE, nullptr, 0, nullptr, 0.f, 0, 0);
        softmax_kernel<256><<<BH * N, 256>>>(attn1);

        // attn2 = softmax(SCALE * q_l @ k_l^T) (256 x 256 x 64)
        gemm(1, M, M, DH,
             ql, DH, (long)H * M * DH, (long)M * DH,
             kl, DH, (long)H * M * DH, (long)M * DH, 1,
             attn2, M, (long)H * M * M, MM2,
             BH, H, SCALE, nullptr, 0, nullptr, 0.f, 0, 0);
        softmax_kernel<256><<<BH * M, 256>>>(attn2);

        // attn3 = softmax(SCALE * q_l @ k^T)   (256 x 1024 x 64)
        gemm(1, M, N, DH,
             ql, DH, (long)H * M * DH, (long)M * DH,
             qkv + D, 3 * D, (long)N * 3 * D, 64, 1,
             attn3, N, (long)H * M * N, (long)M * N,
             BH, H, SCALE, nullptr, 0, nullptr, 0.f, 0, 0);
        softmax_kernel<1024><<<BH * M, 256>>>(attn3);

        // Moore-Penrose pinv of attn2 (6 iterations)
        scal_init_kernel<<<1, 32>>>(scal);
        absrowmax_kernel<<<BH * M, 256>>>(attn2, scal);
        abscolmax_kernel<<<BH, 256>>>(attn2, scal);
        zinit_kernel<<<(BH * M * M) / 256, 256>>>(attn2, scal, zb);

        float* zc = zb;
        float* zn = zb2;
        for (int it = 0; it < 6; it++) {
            // xz = x @ z
            gemm(1, M, M, M, attn2, M, MM2, 0, zc, M, MM2, 0, 0,
                 xz, M, MM2, 0, BH, 1, 1.f, nullptr, 0, nullptr, 0.f, 0, 0);
            // u1 = 7*xz - xz@xz
            gemm(1, M, M, M, xz, M, MM2, 0, xz, M, MM2, 0, 0,
                 u1, M, MM2, 0, BH, 1, -1.f, nullptr, 0, xz, 7.f, 0, 0);
            // u3 = 15*xz - xz@u1
            gemm(1, M, M, M, xz, M, MM2, 0, u1, M, MM2, 0, 0,
                 u3, M, MM2, 0, BH, 1, -1.f, nullptr, 0, xz, 15.f, 0, 0);
            // z' = 3.25*z - 0.25*z@u3
            gemm(1, M, M, M, zc, M, MM2, 0, u3, M, MM2, 0, 0,
                 zn, M, MM2, 0, BH, 1, -0.25f, nullptr, 0, zc, 3.25f, 0, 0);
            float* tmp = zc; zc = zn; zn = tmp;
        }
        // zc holds pinv(attn2) after 6 iterations

        // av = attn3 @ v    (256 x 64 x 1024)
        gemm(0, M, DH, N,
             attn3, N, (long)H * M * N, (long)M * N,
             qkv + 2 * D, 3 * D, (long)N * 3 * D, 64, 0,
             av, DH, (long)H * M * DH, (long)M * DH,
             BH, H, 1.f, nullptr, 0, nullptr, 0.f, 0, 0);

        // conv residual into ctx (B,N,D layout)
        conv_kernel<<<dim3(N / 128, BH), 256>>>(qkv, ckp, ctx);

        // t = attn1 @ pinv  (1024 x 256 x 256)
        gemm(1, N, M, M,
             attn1, M, (long)N * M, 0,
             zc, M, MM2, 0, 0,
             tt, M, (long)N * M, 0,
             BH, 1, 1.f, nullptr, 0, nullptr, 0.f, 0, 0);

        // ctx += t @ av     (1024 x 64 x 256), strided write into (B,N,D)
        gemm(0, N, DH, M,
             tt, M, (long)H * N * M, (long)N * M,
             av, DH, (long)H * M * DH, (long)M * DH, 0,
             ctx, D, (long)N * D, 64,
             BH, H, 1.f, nullptr, 0, nullptr, 0.f, 1, 0);

        // h += (ctx @ out_w + out_b)[:, -L:]   (remap epilogue)
        gemm(1, B * N, D, D, ctx, D, 0, 0, ow, D, 0, 0, 0,
             h, D, 0, 0, 1, 1, 1.f, ob, 0, nullptr, 0.f, 0, 1);

        // FFN
        ln_kernel<<<B * L, 256>>>(h, x2, ln2_s + (long)i * D, ln2_b + (long)i * D);
        gemm(1, B * L, FF, D, x2, D, 0, 0, w1, FF, 0, 0, 0,
             ff, FF, 0, 0, 1, 1, 1.f, b1, 1, nullptr, 0.f, 0, 0);
        gemm(1, B * L, D, FF, ff, FF, 0, 0, w2, D, 0, 0, 0,
             h, D, 0, 0, 1, 1, 1.f, b2, 0, nullptr, 0.f, 1, 0);
    }

    final_partial_kernel<<<dim3(64, B), 256>>>(h, fin_w, part);
    final_reduce_kernel<<<B, 32>>>(part, fin_b, out);
}

// round 9
// speedup vs baseline: 3.7498x; 1.1030x over previous
#include <cuda_runtime.h>
#include <cuda_fp16.h>
#include <cstdint>
#include <math.h>
#include <mma.h>

using namespace nvcuda;

namespace nys {

constexpr int B = 16, L = 1000, D = 512, H = 8, DH = 64;
constexpr int N = 1024, M = 256, PADN = 24, DEPTH = 6, FF = 2048, KC = 33;
constexpr int BH = B * H;
constexpr float SCALE = 0.125f;   // DH^-0.5

// ------------------------- scratch (static device memory) -------------------
__device__ float g_h   [B * L * D];
__device__ float g_xp  [B * N * D];
__device__ float g_x2  [B * L * D];
__device__ float g_qkv [B * N * 3 * D];
__device__ float g_ql  [BH * M * DH];
__device__ float g_kl  [BH * M * DH];
__device__ float g_attn1[BH * N * M];
__device__ float g_attn3[BH * M * N];
__device__ float g_attn2[BH * M * M];
__device__ float g_z   [BH * M * M];
__device__ float g_z2  [BH * M * M];
__device__ float g_xz  [BH * M * M];
__device__ float g_u1  [BH * M * M];
__device__ float g_u3  [BH * M * M];
__device__ float g_av  [BH * M * DH];
__device__ float g_pav [BH * M * DH];
__device__ float g_ctx [B * N * D];
__device__ float g_ff  [B * L * FF];
__device__ float g_scal[2];
__device__ float g_part[B * 64];

// ------------------------- block reduction helpers --------------------------
__device__ __forceinline__ float blkSum(float v, float* sh) {
    int lane = threadIdx.x & 31, w = threadIdx.x >> 5;
#pragma unroll
    for (int o = 16; o; o >>= 1) v += __shfl_xor_sync(0xffffffffu, v, o);
    if (lane == 0) sh[w] = v;
    __syncthreads();
    if (w == 0) {
        float t = (lane < (int)(blockDim.x >> 5)) ? sh[lane] : 0.f;
#pragma unroll
        for (int o = 16; o; o >>= 1) t += __shfl_xor_sync(0xffffffffu, t, o);
        if (lane == 0) sh[32] = t;
    }
    __syncthreads();
    float r = sh[32];
    __syncthreads();
    return r;
}

__device__ __forceinline__ float blkMax(float v, float* sh) {
    int lane = threadIdx.x & 31, w = threadIdx.x >> 5;
#pragma unroll
    for (int o = 16; o; o >>= 1) v = fmaxf(v, __shfl_xor_sync(0xffffffffu, v, o));
    if (lane == 0) sh[w] = v;
    __syncthreads();
    if (w == 0) {
        float t = (lane < (int)(blockDim.x >> 5)) ? sh[lane] : -3.4e38f;
#pragma unroll
        for (int o = 16; o; o >>= 1) t = fmaxf(t, __shfl_xor_sync(0xffffffffu, t, o));
        if (lane == 0) sh[32] = t;
    }
    __syncthreads();
    float r = sh[32];
    __syncthreads();
    return r;
}

// ------------------------- fp16 tensor-core batched GEMM ---------------------
// C = alpha * A(@/@T)B [+ escale*E] [+ bias] [gelu] [accumulate / row-remap]
// A fp32 [m,k] row-major; B fp32 [k,n] (transB=0) or [n,k] (transB=1).
// fp32 -> fp16 RN on staging; fp32 accumulate.
// Register-prefetch + double-buffered smem, one sync per K-tile.
// Fast fragment epilogue when no bias/gelu/remap.
// 256 threads, 8 warps (4x2), warp tile 32 x (NT/2), BM=128, BK=32.
template <int NT>
__global__ void __launch_bounds__(256) hgemm(
    int Kdim,
    const float* __restrict__ A, int lda, long sA1, long sA2,
    const float* __restrict__ Bm, int ldb, long sB1, long sB2, int transB,
    float* __restrict__ C, int ldc, long sC1, long sC2,
    int Hd, float alpha,
    const float* __restrict__ bias, int gelu,
    const float* __restrict__ E, float escale,
    int accumulate, int remap)
{
    constexpr int BM = 128, BK = 32;
    constexpr int LDA = BK + 8;    // 40 halfs
    constexpr int LDB = NT + 8;
    constexpr int MI = 2;          // warp m tiles of 16
    constexpr int NI = NT / 32;    // warp n tiles of 16 (4 or 2)
    constexpr int BREG = NT / 32;  // B float4s per thread per tile

    __shared__ __half sA[2][BM * LDA];
    __shared__ __half sB[2][BK * LDB];
    __shared__ float cpad[8][16 * 20];

    int tid = threadIdx.x;
    int wid = tid >> 5, lane = tid & 31;
    int m0 = blockIdx.y * BM, n0 = blockIdx.x * NT;
    int z = blockIdx.z;
    int bb = z / Hd, hh = z - bb * Hd;
    const float* Ap = A + (long)bb * sA1 + (long)hh * sA2;
    const float* Bp = Bm + (long)bb * sB1 + (long)hh * sB2;
    long coff = (long)bb * sC1 + (long)hh * sC2;

    int wm0 = (wid >> 1) * 32;
    int wn0 = (wid & 1) * (NT / 2);

    wmma::fragment<wmma::accumulator, 16, 16, 16, float> acc[MI][NI];
#pragma unroll
    for (int mi = 0; mi < MI; mi++)
#pragma unroll
        for (int ni = 0; ni < NI; ni++) wmma::fill_fragment(acc[mi][ni], 0.f);

    float4 aR[4], bR[BREG];

    auto loadT = [&](int k0) {
#pragma unroll
        for (int t = 0; t < 4; t++) {
            int i = t * 256 + tid;
            int row = i >> 3, kq = i & 7;
            aR[t] = *(const float4*)(Ap + (long)(m0 + row) * lda + k0 + kq * 4);
        }
        if (transB) {
#pragma unroll
            for (int t = 0; t < BREG; t++) {
                int i = t * 256 + tid;
                int n = i >> 3, kq = i & 7;
                bR[t] = *(const float4*)(Bp + (long)(n0 + n) * ldb + k0 + kq * 4);
            }
        } else {
#pragma unroll
            for (int t = 0; t < BREG; t++) {
                int i = t * 256 + tid;
                int row = i / (NT / 4), c4 = i % (NT / 4);
                bR[t] = *(const float4*)(Bp + (long)(k0 + row) * ldb + n0 + c4 * 4);
            }
        }
    };

    auto storeT = [&](int bf) {
#pragma unroll
        for (int t = 0; t < 4; t++) {
            int i = t * 256 + tid;
            int row = i >> 3, kq = i & 7;
            __half2* dst = (__half2*)&sA[bf][row * LDA + kq * 4];
            dst[0] = __floats2half2_rn(aR[t].x, aR[t].y);
            dst[1] = __floats2half2_rn(aR[t].z, aR[t].w);
        }
        if (transB) {
#pragma unroll
            for (int t = 0; t < BREG; t++) {
                int i = t * 256 + tid;
                int n = i >> 3, kq = i & 7;
                sB[bf][(kq * 4 + 0) * LDB + n] = __float2half_rn(bR[t].x);
                sB[bf][(kq * 4 + 1) * LDB + n] = __float2half_rn(bR[t].y);
                sB[bf][(kq * 4 + 2) * LDB + n] = __float2half_rn(bR[t].z);
                sB[bf][(kq * 4 + 3) * LDB + n] = __float2half_rn(bR[t].w);
            }
        } else {
#pragma unroll
            for (int t = 0; t < BREG; t++) {
                int i = t * 256 + tid;
                int row = i / (NT / 4), c4 = i % (NT / 4);
                __half2* dst = (__half2*)&sB[bf][row * LDB + c4 * 4];
                dst[0] = __floats2half2_rn(bR[t].x, bR[t].y);
                dst[1] = __floats2half2_rn(bR[t].z, bR[t].w);
            }
        }
    };

    loadT(0);
    storeT(0);
    __syncthreads();
    int nk = Kdim / BK;
    for (int c = 0; c < nk; c++) {
        if (c + 1 < nk) loadT((c + 1) * BK);   // LDGs in flight during mma
        int bf = c & 1;
#pragma unroll
        for (int ks = 0; ks < 2; ks++) {
            wmma::fragment<wmma::matrix_a, 16, 16, 16, __half, wmma::row_major> af[MI];
#pragma unroll
            for (int mi = 0; mi < MI; mi++)
                wmma::load_matrix_sync(af[mi], &sA[bf][(wm0 + mi * 16) * LDA + ks * 16], LDA);
#pragma unroll
            for (int ni = 0; ni < NI; ni++) {
                wmma::fragment<wmma::matrix_b, 16, 16, 16, __half, wmma::row_major> bfr;
                wmma::load_matrix_sync(bfr, &sB[bf][(ks * 16) * LDB + wn0 + ni * 16], LDB);
#pragma unroll
                for (int mi = 0; mi < MI; mi++)
                    wmma::mma_sync(acc[mi][ni], af[mi], bfr, acc[mi][ni]);
            }
        }
        if (c + 1 < nk) storeT((c + 1) & 1);   // different buffer; safe pre-sync
        __syncthreads();
    }

    if (!bias && !gelu && !remap) {
        // fast fragment epilogue: alpha, escale*E, accumulate, direct store
#pragma unroll
        for (int mi = 0; mi < MI; mi++) {
#pragma unroll
            for (int ni = 0; ni < NI; ni++) {
                long base = coff + (long)(m0 + wm0 + mi * 16) * ldc + (n0 + wn0 + ni * 16);
#pragma unroll
                for (int e = 0; e < acc[mi][ni].num_elements; e++)
                    acc[mi][ni].x[e] *= alpha;
                if (E) {
                    wmma::fragment<wmma::accumulator, 16, 16, 16, float> ef;
                    wmma::load_matrix_sync(ef, E + base, ldc, wmma::mem_row_major);
#pragma unroll
                    for (int e = 0; e < ef.num_elements; e++)
                        acc[mi][ni].x[e] += escale * ef.x[e];
                }
                if (accumulate) {
                    wmma::fragment<wmma::accumulator, 16, 16, 16, float> cf;
                    wmma::load_matrix_sync(cf, C + base, ldc, wmma::mem_row_major);
#pragma unroll
                    for (int e = 0; e < cf.num_elements; e++)
                        acc[mi][ni].x[e] += cf.x[e];
                }
                wmma::store_matrix_sync(C + base, acc[mi][ni], ldc, wmma::mem_row_major);
            }
        }
        return;
    }

    // slow epilogue: per-warp 16x16 patches staged through smem
#pragma unroll
    for (int mi = 0; mi < MI; mi++) {
#pragma unroll
        for (int ni = 0; ni < NI; ni++) {
            wmma::store_matrix_sync(&cpad[wid][0], acc[mi][ni], 20, wmma::mem_row_major);
            __syncwarp();
#pragma unroll
            for (int j = 0; j < 8; j++) {
                int p = j * 32 + lane;           // 0..255
                int pr = p >> 4, pc = p & 15;
                float v = alpha * cpad[wid][pr * 20 + pc];
                int m = m0 + wm0 + mi * 16 + pr;
                int n = n0 + wn0 + ni * 16 + pc;
                if (E) v += escale * E[coff + (long)m * ldc + n];
                if (bias) v += bias[n];
                if (gelu) v = 0.5f * v * (1.0f + erff(v * 0.70710678118654752f));
                if (remap) {
                    int bI = m >> 10;            // N = 1024
                    int nn = m & 1023;
                    if (nn >= PADN)
                        C[((long)bI * L + (nn - PADN)) * ldc + n] += v;
                } else {
                    long idx = coff + (long)m * ldc + n;
                    if (accumulate) C[idx] += v; else C[idx] = v;
                }
            }
            __syncwarp();
        }
    }
}

// ------------------------- elementwise / reduction kernels -------------------
__global__ void embed_kernel(const int* __restrict__ x, const float* __restrict__ enc,
                             const float* __restrict__ pos, float* __restrict__ h) {
    long idx = (long)blockIdx.x * 256 + threadIdx.x;   // B*L*D total
    int d = (int)(idx % D);
    long bl = idx / D;
    int l = (int)(bl % L);
    h[idx] = enc[(long)x[bl] * D + d] + pos[(long)l * D + d];
}

__global__ void ln_pad_kernel(const float* __restrict__ src, float* __restrict__ dst,
                              const float* __restrict__ s, const float* __restrict__ bia) {
    int row = blockIdx.x;                 // B*N rows
    int b = row >> 10, n = row & 1023;
    int tid = threadIdx.x;                // 256 threads, 2 elems each
    float* out = dst + (long)row * D;
    if (n < PADN) { out[tid] = 0.f; out[tid + 256] = 0.f; return; }
    const float* in = src + ((long)b * L + (n - PADN)) * D;
    __shared__ float sh[33];
    float v0 = in[tid], v1 = in[tid + 256];
    float mu = blkSum(v0 + v1, sh) * (1.0f / D);
    float d0 = v0 - mu, d1 = v1 - mu;
    float var = blkSum(d0 * d0 + d1 * d1, sh) * (1.0f / D);
    float r = rsqrtf(var + 1e-5f);
    out[tid]       = d0 * r * s[tid]       + bia[tid];
    out[tid + 256] = d1 * r * s[tid + 256] + bia[tid + 256];
}

__global__ void ln_kernel(const float* __restrict__ src, float* __restrict__ dst,
                          const float* __restrict__ s, const float* __restrict__ bia) {
    long row = blockIdx.x;                // B*L rows
    int tid = threadIdx.x;
    const float* in = src + row * D;
    float* out = dst + row * D;
    __shared__ float sh[33];
    float v0 = in[tid], v1 = in[tid + 256];
    float mu = blkSum(v0 + v1, sh) * (1.0f / D);
    float d0 = v0 - mu, d1 = v1 - mu;
    float var = blkSum(d0 * d0 + d1 * d1, sh) * (1.0f / D);
    float r = rsqrtf(var + 1e-5f);
    out[tid]       = d0 * r * s[tid]       + bia[tid];
    out[tid + 256] = d1 * r * s[tid + 256] + bia[tid + 256];
}

__global__ void landmark_kernel(const float* __restrict__ qkv,
                                float* __restrict__ ql, float* __restrict__ kl) {
    int idx = blockIdx.x * 256 + threadIdx.x;    // BH*M*DH total
    int d = idx & 63;
    int m = (idx >> 6) & (M - 1);
    int bh = idx >> 14;
    int b = bh >> 3, h = bh & 7;
    const float* base = qkv + ((long)(b * N + m * 4)) * 1536 + h * 64 + d;
    float sq = 0.f, sk = 0.f;
#pragma unroll
    for (int j = 0; j < 4; j++) { sq += base[j * 1536]; sk += base[j * 1536 + 512]; }
    ql[idx] = sq * 0.25f;
    kl[idx] = sk * 0.25f;
}

// softmax over rows of width 256: 1 warp per row, 4 rows per block, float4 IO
__global__ void softmax256_kernel(float* __restrict__ x) {
    int row = blockIdx.x * 4 + (threadIdx.x >> 5);
    int lane = threadIdx.x & 31;
    float4* p = (float4*)(x + (long)row * 256);
    float4 a = p[lane], b = p[lane + 32];
    float mx = fmaxf(fmaxf(fmaxf(a.x, a.y), fmaxf(a.z, a.w)),
                     fmaxf(fmaxf(b.x, b.y), fmaxf(b.z, b.w)));
#pragma unroll
    for (int o = 16; o; o >>= 1) mx = fmaxf(mx, __shfl_xor_sync(0xffffffffu, mx, o));
    a.x = expf(a.x - mx); a.y = expf(a.y - mx); a.z = expf(a.z - mx); a.w = expf(a.w - mx);
    b.x = expf(b.x - mx); b.y = expf(b.y - mx); b.z = expf(b.z - mx); b.w = expf(b.w - mx);
    float s = a.x + a.y + a.z + a.w + b.x + b.y + b.z + b.w;
#pragma unroll
    for (int o = 16; o; o >>= 1) s += __shfl_xor_sync(0xffffffffu, s, o);
    float inv = 1.0f / s;
    a.x *= inv; a.y *= inv; a.z *= inv; a.w *= inv;
    b.x *= inv; b.y *= inv; b.z *= inv; b.w *= inv;
    p[lane] = a; p[lane + 32] = b;
}

// softmax over rows of width 1024: 1 block (256 thr) per row, float4 IO
__global__ void softmax1024_kernel(float* __restrict__ x) {
    int tid = threadIdx.x;
    float4* p = (float4*)(x + (long)blockIdx.x * 1024);
    __shared__ float sh[33];
    float4 v = p[tid];
    float mx = fmaxf(fmaxf(v.x, v.y), fmaxf(v.z, v.w));
    mx = blkMax(mx, sh);
    v.x = expf(v.x - mx); v.y = expf(v.y - mx); v.z = expf(v.z - mx); v.w = expf(v.w - mx);
    float s = blkSum(v.x + v.y + v.z + v.w, sh);
    float inv = 1.0f / s;
    v.x *= inv; v.y *= inv; v.z *= inv; v.w *= inv;
    p[tid] = v;
}

__global__ void scal_init_kernel(float* scal) {
    if (threadIdx.x < 2) scal[threadIdx.x] = 0.f;
}

__global__ void absrowmax_kernel(const float* __restrict__ x, float* scal) {
    long base = (long)blockIdx.x * M;     // BH*M rows
    __shared__ float sh[33];
    float v = fabsf(x[base + threadIdx.x]);
    float s = blkSum(v, sh);
    if (threadIdx.x == 0)
        atomicMax((unsigned int*)&scal[0], __float_as_uint(s));
}

__global__ void abscolmax_kernel(const float* __restrict__ x, float* scal) {
    const float* p = x + (long)blockIdx.x * M * M;   // BH batches
    int j = threadIdx.x;
    float s = 0.f;
    for (int i = 0; i < M; i++) s += fabsf(p[i * M + j]);
    __shared__ float sh[33];
    float m = blkMax(s, sh);
    if (threadIdx.x == 0)
        atomicMax((unsigned int*)&scal[1], __float_as_uint(m));
}

__global__ void zinit_kernel(const float* __restrict__ x, const float* __restrict__ scal,
                             float* __restrict__ z) {
    long idx = (long)blockIdx.x * 256 + threadIdx.x;  // BH*M*M
    float inv = 1.0f / (scal[0] * scal[1]);
    int j = (int)(idx & 255);
    int i = (int)((idx >> 8) & 255);
    long bh = idx >> 16;
    z[idx] = x[(bh << 16) + (long)j * M + i] * inv;
}

__global__ void conv_kernel(const float* __restrict__ qkv, const float* __restrict__ ck,
                            float* __restrict__ ctx) {
    __shared__ float sv[160 * 64];
    __shared__ float sck[KC];
    int bh = blockIdx.y;
    int b = bh >> 3, h = bh & 7;
    int n0 = blockIdx.x * 128;
    int tid = threadIdx.x;
    if (tid < KC) sck[tid] = ck[h * KC + tid];
    for (int i = tid; i < 160 * 64; i += 256) {
        int r = i >> 6, d = i & 63;
        int n = n0 - 16 + r;
        float v = 0.f;
        if (n >= 0 && n < N) v = qkv[((long)(b * N + n)) * 1536 + 1024 + h * 64 + d];
        sv[i] = v;
    }
    __syncthreads();
    for (int o = tid; o < 128 * 64; o += 256) {
        int nl = o >> 6, d = o & 63;
        float s = 0.f;
#pragma unroll
        for (int t = 0; t < KC; t++) s += sck[t] * sv[(nl + t) * 64 + d];
        ctx[((long)(b * N + n0 + nl)) * D + h * 64 + d] = s;
    }
}

__global__ void final_partial_kernel(const float* __restrict__ h, const float* __restrict__ fw,
                                     float* __restrict__ part) {
    int b = blockIdx.y, c = blockIdx.x;   // 64 chunks per batch
    const int CHK = (L * D) / 64;         // 8000
    long base = (long)b * L * D;
    float s = 0.f;
    for (int i = c * CHK + threadIdx.x; i < (c + 1) * CHK; i += 256)
        s += h[base + i] * fw[i];
    __shared__ float sh[33];
    s = blkSum(s, sh);
    if (threadIdx.x == 0) part[b * 64 + c] = s;
}

__global__ void final_reduce_kernel(const float* __restrict__ part, const float* __restrict__ fb,
                                    float* __restrict__ out) {
    int b = blockIdx.x;
    int t = threadIdx.x;  // 32
    float v = part[b * 64 + t] + part[b * 64 + t + 32];
#pragma unroll
    for (int o = 16; o; o >>= 1) v += __shfl_xor_sync(0xffffffffu, v, o);
    if (t == 0) out[b] = v + fb[0];
}

} // namespace nys

// ------------------------- host orchestration --------------------------------
static float* nys_sym(const void* s) {
    void* p = nullptr;
    cudaGetSymbolAddress(&p, s);
    return (float*)p;
}

static void gemm(int cfg128, int Mdim, int Ndim, int K,
                 const float* A, int lda, long sA1, long sA2,
                 const float* Bm, int ldb, long sB1, long sB2, int tB,
                 float* C, int ldc, long sC1, long sC2,
                 int batch, int Hd, float alpha,
                 const float* bias, int gelu, const float* E, float es,
                 int acc, int remap) {
    if (cfg128) {
        dim3 g(Ndim / 128, Mdim / 128, batch);
        nys::hgemm<128><<<g, 256>>>(
            K, A, lda, sA1, sA2, Bm, ldb, sB1, sB2, tB,
            C, ldc, sC1, sC2, Hd, alpha, bias, gelu, E, es, acc, remap);
    } else {
        dim3 g(Ndim / 64, Mdim / 128, batch);
        nys::hgemm<64><<<g, 256>>>(
            K, A, lda, sA1, sA2, Bm, ldb, sB1, sB2, tB,
            C, ldc, sC1, sC2, Hd, alpha, bias, gelu, E, es, acc, remap);
    }
}

extern "C" void kernel_launch(void* const* d_in, const int* in_sizes, int n_in,
                              void* d_out, int out_size) {
    using namespace nys;
    (void)in_sizes; (void)n_in; (void)out_size;

    const int*   xin    = (const int*)  d_in[0];
    const float* enc    = (const float*)d_in[1];
    const float* pos    = (const float*)d_in[2];
    const float* ln1_s  = (const float*)d_in[3];
    const float* ln1_b  = (const float*)d_in[4];
    const float* qkv_w  = (const float*)d_in[5];
    const float* out_w  = (const float*)d_in[6];
    const float* out_b  = (const float*)d_in[7];
    const float* conv_k = (const float*)d_in[8];
    const float* ln2_s  = (const float*)d_in[9];
    const float* ln2_b  = (const float*)d_in[10];
    const float* ff_w1  = (const float*)d_in[11];
    const float* ff_b1  = (const float*)d_in[12];
    const float* ff_w2  = (const float*)d_in[13];
    const float* ff_b2  = (const float*)d_in[14];
    const float* fin_w  = (const float*)d_in[15];
    const float* fin_b  = (const float*)d_in[16];
    float* out = (float*)d_out;

    float* h     = nys_sym(g_h);
    float* xp    = nys_sym(g_xp);
    float* x2    = nys_sym(g_x2);
    float* qkv   = nys_sym(g_qkv);
    float* ql    = nys_sym(g_ql);
    float* kl    = nys_sym(g_kl);
    float* attn1 = nys_sym(g_attn1);
    float* attn3 = nys_sym(g_attn3);
    float* attn2 = nys_sym(g_attn2);
    float* zb    = nys_sym(g_z);
    float* zb2   = nys_sym(g_z2);
    float* xz    = nys_sym(g_xz);
    float* u1    = nys_sym(g_u1);
    float* u3    = nys_sym(g_u3);
    float* av    = nys_sym(g_av);
    float* pav   = nys_sym(g_pav);
    float* ctx   = nys_sym(g_ctx);
    float* ff    = nys_sym(g_ff);
    float* scal  = nys_sym(g_scal);
    float* part  = nys_sym(g_part);

    const long MM2 = (long)M * M;

    embed_kernel<<<(B * L * D) / 256, 256>>>(xin, enc, pos, h);

    for (int i = 0; i < DEPTH; i++) {
        const float* qw  = qkv_w  + (long)i * D * 3 * D;
        const float* ow  = out_w  + (long)i * D * D;
        const float* ob  = out_b  + (long)i * D;
        const float* ckp = conv_k + (long)i * H * KC;
        const float* w1  = ff_w1  + (long)i * D * FF;
        const float* b1  = ff_b1  + (long)i * FF;
        const float* w2  = ff_w2  + (long)i * FF * D;
        const float* b2  = ff_b2  + (long)i * D;

        // LN1 + left-pad into xp (B*N rows)
        ln_pad_kernel<<<B * N, 256>>>(h, xp, ln1_s + (long)i * D, ln1_b + (long)i * D);

        // qkv = xp @ qkv_w   (16384 x 1536 x 512)
        gemm(1, B * N, 3 * D, D, xp, D, 0, 0, qw, 3 * D, 0, 0, 0,
             qkv, 3 * D, 0, 0, 1, 1, 1.f, nullptr, 0, nullptr, 0.f, 0, 0);

        // landmark means (q_l unscaled; SCALE folded into logit alphas)
        landmark_kernel<<<(BH * M * DH) / 256, 256>>>(qkv, ql, kl);

        // attn1 = softmax(SCALE * q @ k_l^T)   (1024 x 256 x 64, batched bh)
        gemm(1, N, M, DH,
             qkv, 3 * D, (long)N * 3 * D, 64,
             kl, DH, (long)H * M * DH, (long)M * DH, 1,
             attn1, M, (long)H * N * M, (long)N * M,
             BH, H, SCALE, nullptr, 0, nullptr, 0.f, 0, 0);
        softmax256_kernel<<<(BH * N) / 4, 128>>>(attn1);

        // attn2 = softmax(SCALE * q_l @ k_l^T) (256 x 256 x 64)
        gemm(1, M, M, DH,
             ql, DH, (long)H * M * DH, (long)M * DH,
             kl, DH, (long)H * M * DH, (long)M * DH, 1,
             attn2, M, (long)H * M * M, MM2,
             BH, H, SCALE, nullptr, 0, nullptr, 0.f, 0, 0);
        softmax256_kernel<<<(BH * M) / 4, 128>>>(attn2);

        // attn3 = softmax(SCALE * q_l @ k^T)   (256 x 1024 x 64)
        gemm(1, M, N, DH,
             ql, DH, (long)H * M * DH, (long)M * DH,
             qkv + D, 3 * D, (long)N * 3 * D, 64, 1,
             attn3, N, (long)H * M * N, (long)M * N,
             BH, H, SCALE, nullptr, 0, nullptr, 0.f, 0, 0);
        softmax1024_kernel<<<BH * M, 256>>>(attn3);

        // Moore-Penrose pinv of attn2 (6 iterations)
        scal_init_kernel<<<1, 32>>>(scal);
        absrowmax_kernel<<<BH * M, 256>>>(attn2, scal);
        abscolmax_kernel<<<BH, 256>>>(attn2, scal);
        zinit_kernel<<<(BH * M * M) / 256, 256>>>(attn2, scal, zb);

        float* zc = zb;
        float* zn = zb2;
        for (int it = 0; it < 6; it++) {
            // xz = x @ z
            gemm(1, M, M, M, attn2, M, MM2, 0, zc, M, MM2, 0, 0,
                 xz, M, MM2, 0, BH, 1, 1.f, nullptr, 0, nullptr, 0.f, 0, 0);
            // u1 = 7*xz - xz@xz
            gemm(1, M, M, M, xz, M, MM2, 0, xz, M, MM2, 0, 0,
                 u1, M, MM2, 0, BH, 1, -1.f, nullptr, 0, xz, 7.f, 0, 0);
            // u3 = 15*xz - xz@u1
            gemm(1, M, M, M, xz, M, MM2, 0, u1, M, MM2, 0, 0,
                 u3, M, MM2, 0, BH, 1, -1.f, nullptr, 0, xz, 15.f, 0, 0);
            // z' = 3.25*z - 0.25*z@u3
            gemm(1, M, M, M, zc, M, MM2, 0, u3, M, MM2, 0, 0,
                 zn, M, MM2, 0, BH, 1, -0.25f, nullptr, 0, zc, 3.25f, 0, 0);
            float* tmp = zc; zc = zn; zn = tmp;
        }
        // zc holds pinv(attn2) after 6 iterations

        // av = attn3 @ v    (256 x 64 x 1024)
        gemm(0, M, DH, N,
             attn3, N, (long)H * M * N, (long)M * N,
             qkv + 2 * D, 3 * D, (long)N * 3 * D, 64, 0,
             av, DH, (long)H * M * DH, (long)M * DH,
             BH, H, 1.f, nullptr, 0, nullptr, 0.f, 0, 0);

        // pav = pinv @ av   (256 x 64 x 256) — reassociated chain
        gemm(0, M, DH, M,
             zc, M, MM2, 0,
             av, DH, (long)M * DH, 0, 0,
             pav, DH, (long)M * DH, 0,
             BH, 1, 1.f, nullptr, 0, nullptr, 0.f, 0, 0);

        // conv residual into ctx (B,N,D layout)
        conv_kernel<<<dim3(N / 128, BH), 256>>>(qkv, ckp, ctx);

        // ctx += attn1 @ pav  (1024 x 64 x 256), strided write into (B,N,D)
        gemm(0, N, DH, M,
             attn1, M, (long)H * N * M, (long)N * M,
             pav, DH, (long)H * M * DH, (long)M * DH, 0,
             ctx, D, (long)N * D, 64,
             BH, H, 1.f, nullptr, 0, nullptr, 0.f, 1, 0);

        // h += (ctx @ out_w + out_b)[:, -L:]   (remap epilogue)
        gemm(1, B * N, D, D, ctx, D, 0, 0, ow, D, 0, 0, 0,
             h, D, 0, 0, 1, 1, 1.f, ob, 0, nullptr, 0.f, 0, 1);

        // FFN
        ln_kernel<<<B * L, 256>>>(h, x2, ln2_s + (long)i * D, ln2_b + (long)i * D);
        gemm(1, B * L, FF, D, x2, D, 0, 0, w1, FF, 0, 0, 0,
             ff, FF, 0, 0, 1, 1, 1.f, b1, 1, nullptr, 0.f, 0, 0);
        gemm(1, B * L, D, FF, ff, FF, 0, 0, w2, D, 0, 0, 0,
             h, D, 0, 0, 1, 1, 1.f, b2, 0, nullptr, 0.f, 1, 0);
    }

    final_partial_kernel<<<dim3(64, B), 256>>>(h, fin_w, part);
    final_reduce_kernel<<<B, 32>>>(part, fin_b, out);
}